// round 12
// baseline (speedup 1.0000x reference)
#include <cuda_runtime.h>
#include <stdint.h>

#define B_MAX 16384
#define IPB 8   // images per block = warps per block (warp w owns image w)

// ---------------- weight scratch (device globals) ----------------
__device__ unsigned g_wp1[8];         // conv1 weight sign bits (25 per oc)
__device__ unsigned g_wp2[16 * 8];    // conv2 weights packed 150b -> 5 words, pad 8
__device__ unsigned g_fw1[120 * 16];  // fc1: 25-bit word per (n, oc)
__device__ unsigned g_fw2[84 * 4];    // fc2: 120 bits -> 4 words per n
__device__ unsigned g_fw3[10 * 3];    // fc3: 84 bits -> 3 words per n

// ---------------- K0: pack all weights into sign bitmasks ----------------
__global__ void pack_weights(const float* __restrict__ w1, const float* __restrict__ w2,
                             const float* __restrict__ f1, const float* __restrict__ f2,
                             const float* __restrict__ f3) {
    int t = blockIdx.x * blockDim.x + threadIdx.x;
    int stride = blockDim.x * gridDim.x;

    if (t < 8) {
        unsigned v = 0;
        if (t < 6)
            for (int i = 0; i < 25; i++) v |= (unsigned)(w1[t * 25 + i] > 0.f) << i;
        g_wp1[t] = v;
    }
    if (t < 16) {  // oc: pack 6x25 bits -> 5x32-bit dense words
        unsigned wi[6];
        for (int ic = 0; ic < 6; ic++) {
            unsigned v = 0;
            for (int i = 0; i < 25; i++) v |= (unsigned)(w2[(t * 6 + ic) * 25 + i] > 0.f) << i;
            wi[ic] = v;
        }
        g_wp2[t * 8 + 0] = wi[0] | (wi[1] << 25);
        g_wp2[t * 8 + 1] = (wi[1] >> 7) | (wi[2] << 18);
        g_wp2[t * 8 + 2] = (wi[2] >> 14) | (wi[3] << 11);
        g_wp2[t * 8 + 3] = (wi[3] >> 21) | (wi[4] << 4) | (wi[5] << 29);
        g_wp2[t * 8 + 4] = (wi[5] >> 3);
        g_wp2[t * 8 + 5] = 0; g_wp2[t * 8 + 6] = 0; g_wp2[t * 8 + 7] = 0;
    }
    for (int w = t; w < 120 * 16; w += stride) {
        int n = w >> 4, oc = w & 15;
        unsigned v = 0;
        for (int i = 0; i < 25; i++) v |= (unsigned)(f1[n * 400 + oc * 25 + i] > 0.f) << i;
        g_fw1[w] = v;
    }
    for (int w = t; w < 84 * 4; w += stride) {
        int n = w >> 2, j = w & 3;
        unsigned v = 0;
        for (int k = 0; k < 32; k++) {
            int i = j * 32 + k;
            if (i < 120) v |= (unsigned)(f2[n * 120 + i] > 0.f) << k;
        }
        g_fw2[w] = v;
    }
    for (int w = t; w < 10 * 3; w += stride) {
        int n = w / 3, j = w % 3;
        unsigned v = 0;
        for (int k = 0; k < 32; k++) {
            int i = j * 32 + k;
            if (i < 84) v |= (unsigned)(f3[n * 84 + i] > 0.f) << k;
        }
        g_fw3[w] = v;
    }
}

// ---------------- mega kernel: warp-private pipeline, no block barriers --
// Warp w processes image (blockIdx*IPB + w) end-to-end. The only
// __syncthreads is after weight staging; all stage boundaries are
// __syncwarp, so warps desynchronize and mixed-stage warps keep every
// SMSP pipe fed (anti-convoy).
__global__ void __launch_bounds__(256, 5) mega_k(const float* __restrict__ x,
                                                 float* __restrict__ out, int B) {
    __shared__ unsigned sx[IPB][32];                     // per-warp packed rows
    __shared__ __align__(16) unsigned sc1[IPB][14][6];   // per-warp conv1 output
    __shared__ unsigned s1w[120 * 17];
    __shared__ unsigned s2w[84 * 5];
    __shared__ unsigned s3w[30];
    __shared__ unsigned swp1[8];
    __shared__ uint4 sw4[16][2];

    int tid = threadIdx.x, warp = tid >> 5, lane = tid & 31;

    // ---- stage weights into smem (single block barrier) ----
    for (int i = tid; i < 120 * 16; i += 256) s1w[(i >> 4) * 17 + (i & 15)] = g_fw1[i];
    for (int i = tid; i < 84 * 4; i += 256) s2w[(i >> 2) * 5 + (i & 3)] = g_fw2[i];
    if (tid < 30) s3w[tid] = g_fw3[tid];
    if (tid >= 32 && tid < 40) swp1[tid - 32] = g_wp1[tid - 32];
    if (tid >= 64 && tid < 96) {
        int k = tid - 64;
        sw4[k >> 1][k & 1] = ((const uint4*)&g_wp2[(k >> 1) * 8])[k & 1];
    }
    __syncthreads();

    int img = blockIdx.x * IPB + warp;
    if (img >= B) return;    // uniform per warp

    // ---- stage 1: pack own image's sign bits into sx[warp] ----
    const float* p = x + (size_t)img * 1024;
#pragma unroll
    for (int it = 0; it < 8; it++) {
        const float* q = p + it * 128 + lane;
        float v0 = q[0], v1 = q[32], v2 = q[64], v3 = q[96];
        unsigned q0 = __ballot_sync(0xffffffffu, v0 > 0.f);
        unsigned q1 = __ballot_sync(0xffffffffu, v1 > 0.f);
        unsigned q2 = __ballot_sync(0xffffffffu, v2 > 0.f);
        unsigned q3 = __ballot_sync(0xffffffffu, v3 > 0.f);
        if (lane == 0) *(uint4*)&sx[warp][it * 4] = make_uint4(q0, q1, q2, q3);
    }
    __syncwarp();

    // ---- stage 2: conv1 + pool + binarize (lanes 0-27: 14 rows x 2 halves)
    if (lane < 28) {
        int py = lane >> 1, h = lane & 1;
        int oxlo = h * 14;

        unsigned rr[6];
#pragma unroll
        for (int k = 0; k < 6; k++) rr[k] = sx[warp][2 * py + k];
        unsigned w[6];
#pragma unroll
        for (int oc = 0; oc < 6; oc++) w[oc] = swp1[oc];

        unsigned o[6] = {0, 0, 0, 0, 0, 0};
#pragma unroll
        for (int dx = 0; dx < 14; dx++) {
            int ox = oxlo + dx;
            unsigned win0 = 0;
#pragma unroll
            for (int j = 0; j < 5; j++) win0 |= ((rr[j] >> ox) & 31u) << (5 * j);
            unsigned win1 = (win0 >> 5) | (((rr[5] >> ox) & 31u) << 20);
            unsigned bit = 1u << (ox >> 1);
#pragma unroll
            for (int oc = 0; oc < 6; oc++) {
                int m = min(__popc(win0 ^ w[oc]), __popc(win1 ^ w[oc]));
                if (m <= 12) o[oc] |= bit;
            }
        }
        // merge the two ox-halves (lane pairs 2k/2k+1, all within mask)
#pragma unroll
        for (int oc = 0; oc < 6; oc++)
            o[oc] |= __shfl_xor_sync(0x0FFFFFFFu, o[oc], 1);
        if (h == 0) {
#pragma unroll
            for (int oc = 0; oc < 6; oc++) sc1[warp][py][oc] = o[oc];
        }
    }
    __syncwarp();

    // ---- stage 3: conv2 + pool + ternarize (lane = cell 0-24) ----
    unsigned W = 0;
    if (lane < 25) {
        int py = lane / 5, px = lane % 5;
        int ox0 = 2 * px;

        unsigned wpk[4][5];
#pragma unroll
        for (int q = 0; q < 4; q++)
#pragma unroll
            for (int w = 0; w < 5; w++) wpk[q][w] = 0u;

#pragma unroll
        for (int icp = 0; icp < 3; icp++) {
            unsigned ra[6], rb[6];
#pragma unroll
            for (int k = 0; k < 6; k++) {
                uint2 v = *(const uint2*)&sc1[warp][2 * py + k][icp * 2];
                ra[k] = v.x; rb[k] = v.y;
            }
#pragma unroll
            for (int h = 0; h < 2; h++) {
                int ox = ox0 + h;
                unsigned va0 = 0, vb0 = 0;
#pragma unroll
                for (int j = 0; j < 5; j++) {
                    va0 |= ((ra[j] >> ox) & 31u) << (5 * j);
                    vb0 |= ((rb[j] >> ox) & 31u) << (5 * j);
                }
                unsigned va1 = (va0 >> 5) | (((ra[5] >> ox) & 31u) << 20);
                unsigned vb1 = (vb0 >> 5) | (((rb[5] >> ox) & 31u) << 20);
                if (icp == 0) {
                    wpk[h][0]     |= va0 | (vb0 << 25);
                    wpk[h][1]     |= vb0 >> 7;
                    wpk[2 + h][0] |= va1 | (vb1 << 25);
                    wpk[2 + h][1] |= vb1 >> 7;
                } else if (icp == 1) {
                    wpk[h][1]     |= va0 << 18;
                    wpk[h][2]     |= (va0 >> 14) | (vb0 << 11);
                    wpk[h][3]     |= vb0 >> 21;
                    wpk[2 + h][1] |= va1 << 18;
                    wpk[2 + h][2] |= (va1 >> 14) | (vb1 << 11);
                    wpk[2 + h][3] |= vb1 >> 21;
                } else {
                    wpk[h][3]     |= (va0 << 4) | (vb0 << 29);
                    wpk[h][4]     |= vb0 >> 3;
                    wpk[2 + h][3] |= (va1 << 4) | (vb1 << 29);
                    wpk[2 + h][4] |= vb1 >> 3;
                }
            }
        }

#pragma unroll
        for (int oc = 0; oc < 16; oc++) {
            uint4 wa = sw4[oc][0];
            unsigned w4v = sw4[oc][1].x;
            int d0 = __popc(wpk[0][0] ^ wa.x) + __popc(wpk[0][1] ^ wa.y)
                   + __popc(wpk[0][2] ^ wa.z) + __popc(wpk[0][3] ^ wa.w)
                   + __popc(wpk[0][4] ^ w4v);
            int d1 = __popc(wpk[1][0] ^ wa.x) + __popc(wpk[1][1] ^ wa.y)
                   + __popc(wpk[1][2] ^ wa.z) + __popc(wpk[1][3] ^ wa.w)
                   + __popc(wpk[1][4] ^ w4v);
            int d2 = __popc(wpk[2][0] ^ wa.x) + __popc(wpk[2][1] ^ wa.y)
                   + __popc(wpk[2][2] ^ wa.z) + __popc(wpk[2][3] ^ wa.w)
                   + __popc(wpk[2][4] ^ w4v);
            int d3 = __popc(wpk[3][0] ^ wa.x) + __popc(wpk[3][1] ^ wa.y)
                   + __popc(wpk[3][2] ^ wa.z) + __popc(wpk[3][3] ^ wa.w)
                   + __popc(wpk[3][4] ^ w4v);
            int m = min(min(d0, d1), min(d2, d3));
            if (m <= 74) W |= 1u << oc;
            if (m != 75) W |= 1u << (16 + oc);
        }
    }

    // ---- stage 4: fc1 -> fc2 -> fc3 (W in-lane; ballots assemble planes) -
    {
        unsigned sp[16], sm[16];
#pragma unroll
        for (int oc = 0; oc < 16; oc++) {
            sp[oc] = __ballot_sync(0xffffffffu, (W >> oc) & 1u);
            sm[oc] = __ballot_sync(0xffffffffu, (W >> (16 + oc)) & 1u);
        }
        int M1 = 0;
#pragma unroll
        for (int i = 0; i < 16; i++) M1 += __popc(sm[i]);

        unsigned p2s[4], p2m[4];
#pragma unroll
        for (int k = 0; k < 4; k++) {
            int n = k * 32 + lane;
            int v = 0;
            bool valid = (n < 120);
            if (valid) {
                int p = 0;
#pragma unroll
                for (int i = 0; i < 16; i++)
                    p += __popc((~(sp[i] ^ s1w[n * 17 + i])) & sm[i]);
                v = 2 * p - M1;
            }
            p2s[k] = __ballot_sync(0xffffffffu, valid && (v > 0));
            p2m[k] = __ballot_sync(0xffffffffu, valid && (v != 0));
        }
        int M2 = __popc(p2m[0]) + __popc(p2m[1]) + __popc(p2m[2]) + __popc(p2m[3]);

        unsigned p3s[3], p3m[3];
#pragma unroll
        for (int k = 0; k < 3; k++) {
            int n = k * 32 + lane;
            int v = 0;
            bool valid = (n < 84);
            if (valid) {
                int p = 0;
#pragma unroll
                for (int j = 0; j < 4; j++)
                    p += __popc((~(p2s[j] ^ s2w[n * 5 + j])) & p2m[j]);
                v = 2 * p - M2;
            }
            p3s[k] = __ballot_sync(0xffffffffu, valid && (v > 0));
            p3m[k] = __ballot_sync(0xffffffffu, valid && (v != 0));
        }
        int M3 = __popc(p3m[0]) + __popc(p3m[1]) + __popc(p3m[2]);

        if (lane < 10) {
            int p = 0;
#pragma unroll
            for (int j = 0; j < 3; j++)
                p += __popc((~(p3s[j] ^ s3w[lane * 3 + j])) & p3m[j]);
            out[(size_t)img * 10 + lane] = (float)(2 * p - M3);
        }
    }
}

// ---------------- launch ----------------
extern "C" void kernel_launch(void* const* d_in, const int* in_sizes, int n_in,
                              void* d_out, int out_size) {
    const float* x  = (const float*)d_in[0];
    const float* w1 = (const float*)d_in[1];
    const float* w2 = (const float*)d_in[2];
    const float* f1 = (const float*)d_in[3];
    const float* f2 = (const float*)d_in[4];
    const float* f3 = (const float*)d_in[5];
    float* out = (float*)d_out;

    int B = in_sizes[0] / 1024;
    if (B > B_MAX) B = B_MAX;

    pack_weights<<<32, 256>>>(w1, w2, f1, f2, f3);

    int blocks = (B + IPB - 1) / IPB;
    mega_k<<<blocks, 256>>>(x, out, B);
}

// round 13
// speedup vs baseline: 1.0662x; 1.0662x over previous
#include <cuda_runtime.h>
#include <stdint.h>

#define B_MAX 16384
#define IPB 8   // images per block

// ---------------- weight scratch (device globals) ----------------
__device__ unsigned g_wp1[8];         // conv1 weight sign bits (25 per oc)
__device__ unsigned g_wp2[16 * 8];    // conv2 weights packed 150b -> 5 words, pad 8
__device__ unsigned g_fw1[120 * 16];  // fc1: 25-bit word per (n, oc)
__device__ unsigned g_fw2[84 * 4];    // fc2: 120 bits -> 4 words per n
__device__ unsigned g_fw3[10 * 3];    // fc3: 84 bits -> 3 words per n

// ---------------- K0: pack all weights into sign bitmasks ----------------
__global__ void pack_weights(const float* __restrict__ w1, const float* __restrict__ w2,
                             const float* __restrict__ f1, const float* __restrict__ f2,
                             const float* __restrict__ f3) {
    int t = blockIdx.x * blockDim.x + threadIdx.x;
    int stride = blockDim.x * gridDim.x;

    if (t < 8) {
        unsigned v = 0;
        if (t < 6)
            for (int i = 0; i < 25; i++) v |= (unsigned)(w1[t * 25 + i] > 0.f) << i;
        g_wp1[t] = v;
    }
    if (t < 16) {  // oc: pack 6x25 bits -> 5x32-bit dense words
        unsigned wi[6];
        for (int ic = 0; ic < 6; ic++) {
            unsigned v = 0;
            for (int i = 0; i < 25; i++) v |= (unsigned)(w2[(t * 6 + ic) * 25 + i] > 0.f) << i;
            wi[ic] = v;
        }
        g_wp2[t * 8 + 0] = wi[0] | (wi[1] << 25);
        g_wp2[t * 8 + 1] = (wi[1] >> 7) | (wi[2] << 18);
        g_wp2[t * 8 + 2] = (wi[2] >> 14) | (wi[3] << 11);
        g_wp2[t * 8 + 3] = (wi[3] >> 21) | (wi[4] << 4) | (wi[5] << 29);
        g_wp2[t * 8 + 4] = (wi[5] >> 3);
        g_wp2[t * 8 + 5] = 0; g_wp2[t * 8 + 6] = 0; g_wp2[t * 8 + 7] = 0;
    }
    for (int w = t; w < 120 * 16; w += stride) {
        int n = w >> 4, oc = w & 15;
        unsigned v = 0;
        for (int i = 0; i < 25; i++) v |= (unsigned)(f1[n * 400 + oc * 25 + i] > 0.f) << i;
        g_fw1[w] = v;
    }
    for (int w = t; w < 84 * 4; w += stride) {
        int n = w >> 2, j = w & 3;
        unsigned v = 0;
        for (int k = 0; k < 32; k++) {
            int i = j * 32 + k;
            if (i < 120) v |= (unsigned)(f2[n * 120 + i] > 0.f) << k;
        }
        g_fw2[w] = v;
    }
    for (int w = t; w < 10 * 3; w += stride) {
        int n = w / 3, j = w % 3;
        unsigned v = 0;
        for (int k = 0; k < 32; k++) {
            int i = j * 32 + k;
            if (i < 84) v |= (unsigned)(f3[n * 84 + i] > 0.f) << k;
        }
        g_fw3[w] = v;
    }
}

// ---------------- mega kernel: pack -> conv1 -> conv2 -> fc --------------
__global__ void __launch_bounds__(256, 5) mega_k(const float* __restrict__ x,
                                                 float* __restrict__ out, int B) {
    __shared__ unsigned sx[IPB][32];
    __shared__ __align__(16) unsigned sc1[IPB][14][6];
    __shared__ unsigned ss2[IPB][25];
    __shared__ unsigned s1w[120 * 17];
    __shared__ unsigned s2w[84 * 5];
    __shared__ unsigned s3w[30];
    __shared__ unsigned swp1[8];
    __shared__ uint4 sw4[16][2];

    int tid = threadIdx.x, warp = tid >> 5, lane = tid & 31;
    int b0 = blockIdx.x * IPB;
    int imax = B - b0; if (imax > IPB) imax = IPB;

    // ---- load weights into smem ----
    for (int i = tid; i < 120 * 16; i += 256) s1w[(i >> 4) * 17 + (i & 15)] = g_fw1[i];
    for (int i = tid; i < 84 * 4; i += 256) s2w[(i >> 2) * 5 + (i & 3)] = g_fw2[i];
    if (tid < 30) s3w[tid] = g_fw3[tid];
    if (tid >= 32 && tid < 40) swp1[tid - 32] = g_wp1[tid - 32];
    if (tid >= 64 && tid < 96) {
        int k = tid - 64;
        sw4[k >> 1][k & 1] = ((const uint4*)&g_wp2[(k >> 1) * 8])[k & 1];
    }

    // ---- stage 1: pack x signs (64 groups of 4 rows over 8 warps) ----
#pragma unroll
    for (int it = 0; it < IPB; it++) {
        int g = warp + it * 8;
        int img = g >> 3, grp = g & 7;
        bool ok = (img < imax);
        const float* p = x + (size_t)(b0 + img) * 1024 + grp * 128 + lane;
        float v0 = ok ? p[0]  : 0.f;
        float v1 = ok ? p[32] : 0.f;
        float v2 = ok ? p[64] : 0.f;
        float v3 = ok ? p[96] : 0.f;
        unsigned q0 = __ballot_sync(0xffffffffu, v0 > 0.f);
        unsigned q1 = __ballot_sync(0xffffffffu, v1 > 0.f);
        unsigned q2 = __ballot_sync(0xffffffffu, v2 > 0.f);
        unsigned q3 = __ballot_sync(0xffffffffu, v3 > 0.f);
        if (lane == 0 && ok) {
            sx[img][grp * 4 + 0] = q0; sx[img][grp * 4 + 1] = q1;
            sx[img][grp * 4 + 2] = q2; sx[img][grp * 4 + 3] = q3;
        }
    }
    __syncthreads();

    // ---- stage 2: conv1 + pool + binarize ----
    // row split across 2 threads (14 ox each), merged via shfl_xor
    if (tid < imax * 28) {
        int img = tid / 28, r = tid % 28;
        int py = r >> 1, h = r & 1;
        int oxlo = h * 14;

        unsigned rr[6];
#pragma unroll
        for (int k = 0; k < 6; k++) rr[k] = sx[img][2 * py + k];
        unsigned w[6];
#pragma unroll
        for (int oc = 0; oc < 6; oc++) w[oc] = swp1[oc];

        unsigned o[6] = {0, 0, 0, 0, 0, 0};
#pragma unroll
        for (int dx = 0; dx < 14; dx++) {
            int ox = oxlo + dx;
            unsigned win0 = 0;
#pragma unroll
            for (int j = 0; j < 5; j++) win0 |= ((rr[j] >> ox) & 31u) << (5 * j);
            unsigned win1 = (win0 >> 5) | (((rr[5] >> ox) & 31u) << 20);
            unsigned bit = 1u << (ox >> 1);
#pragma unroll
            for (int oc = 0; oc < 6; oc++) {
                int m = min(__popc(win0 ^ w[oc]), __popc(win1 ^ w[oc]));
                if (m <= 12) o[oc] |= bit;
            }
        }
#pragma unroll
        for (int oc = 0; oc < 6; oc++)
            o[oc] |= __shfl_xor_sync(0xffffffffu, o[oc], 1);
        if (h == 0) {
#pragma unroll
            for (int oc = 0; oc < 6; oc++) sc1[img][py][oc] = o[oc];
        }
    }
    __syncthreads();

    // ---- stage 3: conv2 + pool + ternarize (IPB*25 = 200 cells, 1 pass) --
    if (tid < imax * 25) {
        int img = tid / 25, cell = tid % 25;
        int py = cell / 5, px = cell % 5;
        int ox0 = 2 * px;

        unsigned wpk[4][5];
#pragma unroll
        for (int q = 0; q < 4; q++)
#pragma unroll
            for (int w = 0; w < 5; w++) wpk[q][w] = 0u;

#pragma unroll
        for (int icp = 0; icp < 3; icp++) {
            unsigned ra[6], rb[6];
#pragma unroll
            for (int k = 0; k < 6; k++) {
                uint2 v = *(const uint2*)&sc1[img][2 * py + k][icp * 2];
                ra[k] = v.x; rb[k] = v.y;
            }
#pragma unroll
            for (int h = 0; h < 2; h++) {
                int ox = ox0 + h;
                unsigned va0 = 0, vb0 = 0;
#pragma unroll
                for (int j = 0; j < 5; j++) {
                    va0 |= ((ra[j] >> ox) & 31u) << (5 * j);
                    vb0 |= ((rb[j] >> ox) & 31u) << (5 * j);
                }
                unsigned va1 = (va0 >> 5) | (((ra[5] >> ox) & 31u) << 20);
                unsigned vb1 = (vb0 >> 5) | (((rb[5] >> ox) & 31u) << 20);
                if (icp == 0) {
                    wpk[h][0]     |= va0 | (vb0 << 25);
                    wpk[h][1]     |= vb0 >> 7;
                    wpk[2 + h][0] |= va1 | (vb1 << 25);
                    wpk[2 + h][1] |= vb1 >> 7;
                } else if (icp == 1) {
                    wpk[h][1]     |= va0 << 18;
                    wpk[h][2]     |= (va0 >> 14) | (vb0 << 11);
                    wpk[h][3]     |= vb0 >> 21;
                    wpk[2 + h][1] |= va1 << 18;
                    wpk[2 + h][2] |= (va1 >> 14) | (vb1 << 11);
                    wpk[2 + h][3] |= vb1 >> 21;
                } else {
                    wpk[h][3]     |= (va0 << 4) | (vb0 << 29);
                    wpk[h][4]     |= vb0 >> 3;
                    wpk[2 + h][3] |= (va1 << 4) | (vb1 << 29);
                    wpk[2 + h][4] |= vb1 >> 3;
                }
            }
        }

        // oc loop, software-pipelined weight loads (hide 29-cyc LDS latency)
        unsigned word = 0;
        uint4 wa = sw4[0][0];
        unsigned w4v = sw4[0][1].x;
#pragma unroll
        for (int oc = 0; oc < 16; oc++) {
            uint4 wan;
            unsigned w4n;
            if (oc < 15) { wan = sw4[oc + 1][0]; w4n = sw4[oc + 1][1].x; }
            int d0 = __popc(wpk[0][0] ^ wa.x) + __popc(wpk[0][1] ^ wa.y)
                   + __popc(wpk[0][2] ^ wa.z) + __popc(wpk[0][3] ^ wa.w)
                   + __popc(wpk[0][4] ^ w4v);
            int d1 = __popc(wpk[1][0] ^ wa.x) + __popc(wpk[1][1] ^ wa.y)
                   + __popc(wpk[1][2] ^ wa.z) + __popc(wpk[1][3] ^ wa.w)
                   + __popc(wpk[1][4] ^ w4v);
            int d2 = __popc(wpk[2][0] ^ wa.x) + __popc(wpk[2][1] ^ wa.y)
                   + __popc(wpk[2][2] ^ wa.z) + __popc(wpk[2][3] ^ wa.w)
                   + __popc(wpk[2][4] ^ w4v);
            int d3 = __popc(wpk[3][0] ^ wa.x) + __popc(wpk[3][1] ^ wa.y)
                   + __popc(wpk[3][2] ^ wa.z) + __popc(wpk[3][3] ^ wa.w)
                   + __popc(wpk[3][4] ^ w4v);
            int m = min(min(d0, d1), min(d2, d3));
            if (m <= 74) word |= 1u << oc;
            if (m != 75) word |= 1u << (16 + oc);
            if (oc < 15) { wa = wan; w4v = w4n; }
        }
        ss2[img][cell] = word;
    }
    __syncthreads();

    // ---- stage 4: fc1 -> fc2 -> fc3, one warp per image ----
    {
        int img = warp;
        if (img < imax) {
            unsigned W = (lane < 25) ? ss2[img][lane] : 0u;
            unsigned sp[16], sm[16];
#pragma unroll
            for (int oc = 0; oc < 16; oc++) {
                sp[oc] = __ballot_sync(0xffffffffu, (W >> oc) & 1u);
                sm[oc] = __ballot_sync(0xffffffffu, (W >> (16 + oc)) & 1u);
            }
            int M1 = 0;
#pragma unroll
            for (int i = 0; i < 16; i++) M1 += __popc(sm[i]);

            unsigned p2s[4], p2m[4];
#pragma unroll
            for (int k = 0; k < 4; k++) {
                int n = k * 32 + lane;
                int v = 0;
                bool valid = (n < 120);
                if (valid) {
                    int p = 0;
#pragma unroll
                    for (int i = 0; i < 16; i++)
                        p += __popc((~(sp[i] ^ s1w[n * 17 + i])) & sm[i]);
                    v = 2 * p - M1;
                }
                p2s[k] = __ballot_sync(0xffffffffu, valid && (v > 0));
                p2m[k] = __ballot_sync(0xffffffffu, valid && (v != 0));
            }
            int M2 = __popc(p2m[0]) + __popc(p2m[1]) + __popc(p2m[2]) + __popc(p2m[3]);

            unsigned p3s[3], p3m[3];
#pragma unroll
            for (int k = 0; k < 3; k++) {
                int n = k * 32 + lane;
                int v = 0;
                bool valid = (n < 84);
                if (valid) {
                    int p = 0;
#pragma unroll
                    for (int j = 0; j < 4; j++)
                        p += __popc((~(p2s[j] ^ s2w[n * 5 + j])) & p2m[j]);
                    v = 2 * p - M2;
                }
                p3s[k] = __ballot_sync(0xffffffffu, valid && (v > 0));
                p3m[k] = __ballot_sync(0xffffffffu, valid && (v != 0));
            }
            int M3 = __popc(p3m[0]) + __popc(p3m[1]) + __popc(p3m[2]);

            if (lane < 10) {
                int p = 0;
#pragma unroll
                for (int j = 0; j < 3; j++)
                    p += __popc((~(p3s[j] ^ s3w[lane * 3 + j])) & p3m[j]);
                out[(size_t)(b0 + img) * 10 + lane] = (float)(2 * p - M3);
            }
        }
    }
}

// ---------------- launch ----------------
extern "C" void kernel_launch(void* const* d_in, const int* in_sizes, int n_in,
                              void* d_out, int out_size) {
    const float* x  = (const float*)d_in[0];
    const float* w1 = (const float*)d_in[1];
    const float* w2 = (const float*)d_in[2];
    const float* f1 = (const float*)d_in[3];
    const float* f2 = (const float*)d_in[4];
    const float* f3 = (const float*)d_in[5];
    float* out = (float*)d_out;

    int B = in_sizes[0] / 1024;
    if (B > B_MAX) B = B_MAX;

    pack_weights<<<32, 256>>>(w1, w2, f1, f2, f3);

    int blocks = (B + IPB - 1) / IPB;
    mega_k<<<blocks, 256>>>(x, out, B);
}

// round 14
// speedup vs baseline: 1.1830x; 1.1095x over previous
#include <cuda_runtime.h>
#include <stdint.h>

#define B_MAX 16384
#define IPB 8   // images per block

__device__ __forceinline__ void csa(unsigned& s, unsigned& c,
                                    unsigned a, unsigned b, unsigned d) {
    s = a ^ b ^ d;                      // LOP3 0x96
    c = (a & b) | (d & (a ^ b));        // LOP3 0xE8 (majority)
}

// ---------------- weight scratch (device globals) ----------------
__device__ unsigned g_wp1[8];         // conv1 weight sign bits (25 per oc)
__device__ unsigned g_wp2[16 * 8];    // conv2 weights packed 150b -> 5 words, pad 8
__device__ unsigned g_fw1[120 * 16];  // fc1: 25-bit word per (n, oc)
__device__ unsigned g_fw2[84 * 4];    // fc2: 120 bits -> 4 words per n
__device__ unsigned g_fw3[10 * 3];    // fc3: 84 bits -> 3 words per n

// ---------------- K0: pack all weights into sign bitmasks ----------------
__global__ void pack_weights(const float* __restrict__ w1, const float* __restrict__ w2,
                             const float* __restrict__ f1, const float* __restrict__ f2,
                             const float* __restrict__ f3) {
    int t = blockIdx.x * blockDim.x + threadIdx.x;
    int stride = blockDim.x * gridDim.x;

    if (t < 8) {
        unsigned v = 0;
        if (t < 6)
            for (int i = 0; i < 25; i++) v |= (unsigned)(w1[t * 25 + i] > 0.f) << i;
        g_wp1[t] = v;
    }
    if (t < 16) {  // oc: pack 6x25 bits -> 5x32-bit dense words
        unsigned wi[6];
        for (int ic = 0; ic < 6; ic++) {
            unsigned v = 0;
            for (int i = 0; i < 25; i++) v |= (unsigned)(w2[(t * 6 + ic) * 25 + i] > 0.f) << i;
            wi[ic] = v;
        }
        g_wp2[t * 8 + 0] = wi[0] | (wi[1] << 25);
        g_wp2[t * 8 + 1] = (wi[1] >> 7) | (wi[2] << 18);
        g_wp2[t * 8 + 2] = (wi[2] >> 14) | (wi[3] << 11);
        g_wp2[t * 8 + 3] = (wi[3] >> 21) | (wi[4] << 4) | (wi[5] << 29);
        g_wp2[t * 8 + 4] = (wi[5] >> 3);
        g_wp2[t * 8 + 5] = 0; g_wp2[t * 8 + 6] = 0; g_wp2[t * 8 + 7] = 0;
    }
    for (int w = t; w < 120 * 16; w += stride) {
        int n = w >> 4, oc = w & 15;
        unsigned v = 0;
        for (int i = 0; i < 25; i++) v |= (unsigned)(f1[n * 400 + oc * 25 + i] > 0.f) << i;
        g_fw1[w] = v;
    }
    for (int w = t; w < 84 * 4; w += stride) {
        int n = w >> 2, j = w & 3;
        unsigned v = 0;
        for (int k = 0; k < 32; k++) {
            int i = j * 32 + k;
            if (i < 120) v |= (unsigned)(f2[n * 120 + i] > 0.f) << k;
        }
        g_fw2[w] = v;
    }
    for (int w = t; w < 10 * 3; w += stride) {
        int n = w / 3, j = w % 3;
        unsigned v = 0;
        for (int k = 0; k < 32; k++) {
            int i = j * 32 + k;
            if (i < 84) v |= (unsigned)(f3[n * 84 + i] > 0.f) << k;
        }
        g_fw3[w] = v;
    }
}

// ---------------- mega kernel: pack -> conv1 -> conv2 -> fc --------------
__global__ void __launch_bounds__(256, 5) mega_k(const float* __restrict__ x,
                                                 float* __restrict__ out, int B) {
    __shared__ unsigned sx[IPB][32];
    __shared__ __align__(16) unsigned sc1[IPB][14][6];
    __shared__ unsigned ss2[IPB][25];
    __shared__ unsigned s1w[120 * 17];
    __shared__ unsigned s2w[84 * 5];
    __shared__ unsigned s3w[30];
    __shared__ unsigned swp1[8];
    __shared__ uint4 sw4[16][2];

    int tid = threadIdx.x, warp = tid >> 5, lane = tid & 31;
    int b0 = blockIdx.x * IPB;
    int imax = B - b0; if (imax > IPB) imax = IPB;

    // ---- load weights into smem ----
    for (int i = tid; i < 120 * 16; i += 256) s1w[(i >> 4) * 17 + (i & 15)] = g_fw1[i];
    for (int i = tid; i < 84 * 4; i += 256) s2w[(i >> 2) * 5 + (i & 3)] = g_fw2[i];
    if (tid < 30) s3w[tid] = g_fw3[tid];
    if (tid >= 32 && tid < 40) swp1[tid - 32] = g_wp1[tid - 32];
    if (tid >= 64 && tid < 96) {
        int k = tid - 64;
        sw4[k >> 1][k & 1] = ((const uint4*)&g_wp2[(k >> 1) * 8])[k & 1];
    }

    // ---- stage 1: pack x signs ----
#pragma unroll
    for (int it = 0; it < IPB; it++) {
        int g = warp + it * 8;
        int img = g >> 3, grp = g & 7;
        bool ok = (img < imax);
        const float* p = x + (size_t)(b0 + img) * 1024 + grp * 128 + lane;
        float v0 = ok ? p[0]  : 0.f;
        float v1 = ok ? p[32] : 0.f;
        float v2 = ok ? p[64] : 0.f;
        float v3 = ok ? p[96] : 0.f;
        unsigned q0 = __ballot_sync(0xffffffffu, v0 > 0.f);
        unsigned q1 = __ballot_sync(0xffffffffu, v1 > 0.f);
        unsigned q2 = __ballot_sync(0xffffffffu, v2 > 0.f);
        unsigned q3 = __ballot_sync(0xffffffffu, v3 > 0.f);
        if (lane == 0 && ok) {
            sx[img][grp * 4 + 0] = q0; sx[img][grp * 4 + 1] = q1;
            sx[img][grp * 4 + 2] = q2; sx[img][grp * 4 + 3] = q3;
        }
    }
    __syncthreads();

    // ---- stage 2: conv1 + pool + binarize ----
    if (tid < imax * 28) {
        int img = tid / 28, r = tid % 28;
        int py = r >> 1, h = r & 1;
        int oxlo = h * 14;

        unsigned rr[6];
#pragma unroll
        for (int k = 0; k < 6; k++) rr[k] = sx[img][2 * py + k];
        unsigned w[6];
#pragma unroll
        for (int oc = 0; oc < 6; oc++) w[oc] = swp1[oc];

        unsigned o[6] = {0, 0, 0, 0, 0, 0};
#pragma unroll
        for (int dx = 0; dx < 14; dx++) {
            int ox = oxlo + dx;
            unsigned win0 = 0;
#pragma unroll
            for (int j = 0; j < 5; j++) win0 |= ((rr[j] >> ox) & 31u) << (5 * j);
            unsigned win1 = (win0 >> 5) | (((rr[5] >> ox) & 31u) << 20);
            unsigned bit = 1u << (ox >> 1);
#pragma unroll
            for (int oc = 0; oc < 6; oc++) {
                int m = min(__popc(win0 ^ w[oc]), __popc(win1 ^ w[oc]));
                if (m <= 12) o[oc] |= bit;
            }
        }
#pragma unroll
        for (int oc = 0; oc < 6; oc++)
            o[oc] |= __shfl_xor_sync(0xffffffffu, o[oc], 1);
        if (h == 0) {
#pragma unroll
            for (int oc = 0; oc < 6; oc++) sc1[img][py][oc] = o[oc];
        }
    }
    __syncthreads();

    // ---- stage 3: conv2 + pool + ternarize (IPB*25 = 200 cells) ----
    if (tid < imax * 25) {
        int img = tid / 25, cell = tid % 25;
        int py = cell / 5, px = cell % 5;
        int ox0 = 2 * px;

        unsigned wpk[4][5];
#pragma unroll
        for (int q = 0; q < 4; q++)
#pragma unroll
            for (int w = 0; w < 5; w++) wpk[q][w] = 0u;

#pragma unroll
        for (int icp = 0; icp < 3; icp++) {
            unsigned ra[6], rb[6];
#pragma unroll
            for (int k = 0; k < 6; k++) {
                uint2 v = *(const uint2*)&sc1[img][2 * py + k][icp * 2];
                ra[k] = v.x; rb[k] = v.y;
            }
#pragma unroll
            for (int h = 0; h < 2; h++) {
                int ox = ox0 + h;
                unsigned va0 = 0, vb0 = 0;
#pragma unroll
                for (int j = 0; j < 5; j++) {
                    va0 |= ((ra[j] >> ox) & 31u) << (5 * j);
                    vb0 |= ((rb[j] >> ox) & 31u) << (5 * j);
                }
                unsigned va1 = (va0 >> 5) | (((ra[5] >> ox) & 31u) << 20);
                unsigned vb1 = (vb0 >> 5) | (((rb[5] >> ox) & 31u) << 20);
                if (icp == 0) {
                    wpk[h][0]     |= va0 | (vb0 << 25);
                    wpk[h][1]     |= vb0 >> 7;
                    wpk[2 + h][0] |= va1 | (vb1 << 25);
                    wpk[2 + h][1] |= vb1 >> 7;
                } else if (icp == 1) {
                    wpk[h][1]     |= va0 << 18;
                    wpk[h][2]     |= (va0 >> 14) | (vb0 << 11);
                    wpk[h][3]     |= vb0 >> 21;
                    wpk[2 + h][1] |= va1 << 18;
                    wpk[2 + h][2] |= (va1 >> 14) | (vb1 << 11);
                    wpk[2 + h][3] |= vb1 >> 21;
                } else {
                    wpk[h][3]     |= (va0 << 4) | (vb0 << 29);
                    wpk[h][4]     |= vb0 >> 3;
                    wpk[2 + h][3] |= (va1 << 4) | (vb1 << 29);
                    wpk[2 + h][4] |= vb1 >> 3;
                }
            }
        }

        // oc loop: prefetched weights + CSA popcount (5 POPC -> 3 per window)
        unsigned word = 0;
        uint4 wa = sw4[0][0];
        unsigned w4v = sw4[0][1].x;
#pragma unroll
        for (int oc = 0; oc < 16; oc++) {
            uint4 wan;
            unsigned w4n;
            if (oc < 15) { wan = sw4[oc + 1][0]; w4n = sw4[oc + 1][1].x; }
            int d[4];
#pragma unroll
            for (int q = 0; q < 4; q++) {
                unsigned x0 = wpk[q][0] ^ wa.x;
                unsigned x1 = wpk[q][1] ^ wa.y;
                unsigned x2 = wpk[q][2] ^ wa.z;
                unsigned x3 = wpk[q][3] ^ wa.w;
                unsigned x4 = wpk[q][4] ^ w4v;
                unsigned s1, c1, s2, c2;
                csa(s1, c1, x0, x1, x2);
                csa(s2, c2, s1, x3, x4);
                d[q] = __popc(s2) + 2 * (__popc(c1) + __popc(c2));
            }
            int m = min(min(d[0], d[1]), min(d[2], d[3]));
            if (m <= 74) word |= 1u << oc;
            if (m != 75) word |= 1u << (16 + oc);
            if (oc < 15) { wa = wan; w4v = w4n; }
        }
        ss2[img][cell] = word;
    }
    __syncthreads();

    // ---- stage 4: fc1 -> fc2 -> fc3, one warp per image ----
    {
        int img = warp;
        if (img < imax) {
            unsigned W = (lane < 25) ? ss2[img][lane] : 0u;
            unsigned sp[16], sm[16];
#pragma unroll
            for (int oc = 0; oc < 16; oc++) {
                sp[oc] = __ballot_sync(0xffffffffu, (W >> oc) & 1u);
                sm[oc] = __ballot_sync(0xffffffffu, (W >> (16 + oc)) & 1u);
            }
            // M1 via Harley-Seal (16 -> 8 POPC)
            int M1;
            {
                unsigned sA, cA, sB, cB, sC, cC, sD, cD;
                csa(sA, cA, sm[0], sm[1], sm[2]);
                csa(sB, cB, sm[3], sm[4], sm[5]);
                csa(sC, cC, sA, sB, sm[6]);
                csa(sD, cD, cA, cB, cC);
                M1 = __popc(sC) + __popc(sm[7]) + 2 * __popc(sD) + 4 * __popc(cD);
                csa(sA, cA, sm[8], sm[9], sm[10]);
                csa(sB, cB, sm[11], sm[12], sm[13]);
                csa(sC, cC, sA, sB, sm[14]);
                csa(sD, cD, cA, cB, cC);
                M1 += __popc(sC) + __popc(sm[15]) + 2 * __popc(sD) + 4 * __popc(cD);
            }

            unsigned p2s[4], p2m[4];
#pragma unroll
            for (int k = 0; k < 4; k++) {
                int n = k * 32 + lane;
                int v = 0;
                bool valid = (n < 120);
                if (valid) {
                    unsigned t[16];
#pragma unroll
                    for (int i = 0; i < 16; i++)
                        t[i] = (~(sp[i] ^ s1w[n * 17 + i])) & sm[i];
                    unsigned sA, cA, sB, cB, sC, cC, sD, cD;
                    csa(sA, cA, t[0], t[1], t[2]);
                    csa(sB, cB, t[3], t[4], t[5]);
                    csa(sC, cC, sA, sB, t[6]);
                    csa(sD, cD, cA, cB, cC);
                    int p = __popc(sC) + __popc(t[7]) + 2 * __popc(sD) + 4 * __popc(cD);
                    csa(sA, cA, t[8], t[9], t[10]);
                    csa(sB, cB, t[11], t[12], t[13]);
                    csa(sC, cC, sA, sB, t[14]);
                    csa(sD, cD, cA, cB, cC);
                    p += __popc(sC) + __popc(t[15]) + 2 * __popc(sD) + 4 * __popc(cD);
                    v = 2 * p - M1;
                }
                p2s[k] = __ballot_sync(0xffffffffu, valid && (v > 0));
                p2m[k] = __ballot_sync(0xffffffffu, valid && (v != 0));
            }
            // M2 via CSA (4 -> 3 POPC)
            int M2;
            {
                unsigned s, c;
                csa(s, c, p2m[0], p2m[1], p2m[2]);
                M2 = __popc(s) + __popc(p2m[3]) + 2 * __popc(c);
            }

            unsigned p3s[3], p3m[3];
#pragma unroll
            for (int k = 0; k < 3; k++) {
                int n = k * 32 + lane;
                int v = 0;
                bool valid = (n < 84);
                if (valid) {
                    unsigned t0 = (~(p2s[0] ^ s2w[n * 5 + 0])) & p2m[0];
                    unsigned t1 = (~(p2s[1] ^ s2w[n * 5 + 1])) & p2m[1];
                    unsigned t2 = (~(p2s[2] ^ s2w[n * 5 + 2])) & p2m[2];
                    unsigned t3 = (~(p2s[3] ^ s2w[n * 5 + 3])) & p2m[3];
                    unsigned s, c;
                    csa(s, c, t0, t1, t2);
                    int p = __popc(s) + __popc(t3) + 2 * __popc(c);
                    v = 2 * p - M2;
                }
                p3s[k] = __ballot_sync(0xffffffffu, valid && (v > 0));
                p3m[k] = __ballot_sync(0xffffffffu, valid && (v != 0));
            }
            // M3 via CSA (3 -> 2 POPC)
            int M3;
            {
                unsigned s, c;
                csa(s, c, p3m[0], p3m[1], p3m[2]);
                M3 = __popc(s) + 2 * __popc(c);
            }

            if (lane < 10) {
                unsigned t0 = (~(p3s[0] ^ s3w[lane * 3 + 0])) & p3m[0];
                unsigned t1 = (~(p3s[1] ^ s3w[lane * 3 + 1])) & p3m[1];
                unsigned t2 = (~(p3s[2] ^ s3w[lane * 3 + 2])) & p3m[2];
                unsigned s, c;
                csa(s, c, t0, t1, t2);
                int p = __popc(s) + 2 * __popc(c);
                out[(size_t)(b0 + img) * 10 + lane] = (float)(2 * p - M3);
            }
        }
    }
}

// ---------------- launch ----------------
extern "C" void kernel_launch(void* const* d_in, const int* in_sizes, int n_in,
                              void* d_out, int out_size) {
    const float* x  = (const float*)d_in[0];
    const float* w1 = (const float*)d_in[1];
    const float* w2 = (const float*)d_in[2];
    const float* f1 = (const float*)d_in[3];
    const float* f2 = (const float*)d_in[4];
    const float* f3 = (const float*)d_in[5];
    float* out = (float*)d_out;

    int B = in_sizes[0] / 1024;
    if (B > B_MAX) B = B_MAX;

    pack_weights<<<32, 256>>>(w1, w2, f1, f2, f3);

    int blocks = (B + IPB - 1) / IPB;
    mega_k<<<blocks, 256>>>(x, out, B);
}

// round 15
// speedup vs baseline: 1.2213x; 1.0324x over previous
#include <cuda_runtime.h>
#include <stdint.h>

#define B_MAX 16384
#define IPB 8   // images per block

__device__ __forceinline__ void csa(unsigned& s, unsigned& c,
                                    unsigned a, unsigned b, unsigned d) {
    s = a ^ b ^ d;                      // LOP3 0x96
    c = (a & b) | (d & (a ^ b));        // LOP3 0xE8 (majority)
}

// ---------------- weight scratch (device globals) ----------------
__device__ unsigned g_wm1[6 * 25];    // conv1 weight sign BROADCAST masks (0 / ~0)
__device__ unsigned g_wp2[16 * 8];    // conv2 weights packed 150b -> 5 words, pad 8
__device__ unsigned g_fw1[120 * 16];  // fc1: 25-bit word per (n, oc)
__device__ unsigned g_fw2[84 * 4];    // fc2: 120 bits -> 4 words per n
__device__ unsigned g_fw3[10 * 3];    // fc3: 84 bits -> 3 words per n

// ---------------- K0: pack all weights ----------------
__global__ void pack_weights(const float* __restrict__ w1, const float* __restrict__ w2,
                             const float* __restrict__ f1, const float* __restrict__ f2,
                             const float* __restrict__ f3) {
    int t = blockIdx.x * blockDim.x + threadIdx.x;
    int stride = blockDim.x * gridDim.x;

    if (t < 150) {   // conv1 masks: oc = t/25, tap = t%25
        g_wm1[t] = (w1[t] > 0.f) ? 0xffffffffu : 0u;   // w1 is [6][25] row-major = t
    }
    if (t < 16) {  // oc: pack 6x25 bits -> 5x32-bit dense words
        unsigned wi[6];
        for (int ic = 0; ic < 6; ic++) {
            unsigned v = 0;
            for (int i = 0; i < 25; i++) v |= (unsigned)(w2[(t * 6 + ic) * 25 + i] > 0.f) << i;
            wi[ic] = v;
        }
        g_wp2[t * 8 + 0] = wi[0] | (wi[1] << 25);
        g_wp2[t * 8 + 1] = (wi[1] >> 7) | (wi[2] << 18);
        g_wp2[t * 8 + 2] = (wi[2] >> 14) | (wi[3] << 11);
        g_wp2[t * 8 + 3] = (wi[3] >> 21) | (wi[4] << 4) | (wi[5] << 29);
        g_wp2[t * 8 + 4] = (wi[5] >> 3);
        g_wp2[t * 8 + 5] = 0; g_wp2[t * 8 + 6] = 0; g_wp2[t * 8 + 7] = 0;
    }
    for (int w = t; w < 120 * 16; w += stride) {
        int n = w >> 4, oc = w & 15;
        unsigned v = 0;
        for (int i = 0; i < 25; i++) v |= (unsigned)(f1[n * 400 + oc * 25 + i] > 0.f) << i;
        g_fw1[w] = v;
    }
    for (int w = t; w < 84 * 4; w += stride) {
        int n = w >> 2, j = w & 3;
        unsigned v = 0;
        for (int k = 0; k < 32; k++) {
            int i = j * 32 + k;
            if (i < 120) v |= (unsigned)(f2[n * 120 + i] > 0.f) << k;
        }
        g_fw2[w] = v;
    }
    for (int w = t; w < 10 * 3; w += stride) {
        int n = w / 3, j = w % 3;
        unsigned v = 0;
        for (int k = 0; k < 32; k++) {
            int i = j * 32 + k;
            if (i < 84) v |= (unsigned)(f3[n * 84 + i] > 0.f) << k;
        }
        g_fw3[w] = v;
    }
}

// ---------------- mega kernel: pack -> conv1(bitsliced) -> conv2 -> fc ---
__global__ void __launch_bounds__(256, 4) mega_k(const float* __restrict__ x,
                                                 float* __restrict__ out, int B) {
    __shared__ unsigned sx[IPB][32];
    __shared__ __align__(16) unsigned sc1[IPB][14][6];
    __shared__ unsigned ss2[IPB][25];
    __shared__ unsigned s1w[120 * 17];
    __shared__ unsigned s2w[84 * 5];
    __shared__ unsigned s3w[30];
    __shared__ unsigned swm1[6 * 25];
    __shared__ uint4 sw4[16][2];

    int tid = threadIdx.x, warp = tid >> 5, lane = tid & 31;
    int b0 = blockIdx.x * IPB;
    int imax = B - b0; if (imax > IPB) imax = IPB;

    // ---- load weights into smem ----
    for (int i = tid; i < 120 * 16; i += 256) s1w[(i >> 4) * 17 + (i & 15)] = g_fw1[i];
    for (int i = tid; i < 84 * 4; i += 256) s2w[(i >> 2) * 5 + (i & 3)] = g_fw2[i];
    if (tid < 30) s3w[tid] = g_fw3[tid];
    if (tid < 150) swm1[tid] = g_wm1[tid];
    if (tid >= 160 && tid < 192) {
        int k = tid - 160;
        sw4[k >> 1][k & 1] = ((const uint4*)&g_wp2[(k >> 1) * 8])[k & 1];
    }

    // ---- stage 1: pack x signs ----
#pragma unroll
    for (int it = 0; it < IPB; it++) {
        int g = warp + it * 8;
        int img = g >> 3, grp = g & 7;
        bool ok = (img < imax);
        const float* p = x + (size_t)(b0 + img) * 1024 + grp * 128 + lane;
        float v0 = ok ? p[0]  : 0.f;
        float v1 = ok ? p[32] : 0.f;
        float v2 = ok ? p[64] : 0.f;
        float v3 = ok ? p[96] : 0.f;
        unsigned q0 = __ballot_sync(0xffffffffu, v0 > 0.f);
        unsigned q1 = __ballot_sync(0xffffffffu, v1 > 0.f);
        unsigned q2 = __ballot_sync(0xffffffffu, v2 > 0.f);
        unsigned q3 = __ballot_sync(0xffffffffu, v3 > 0.f);
        if (lane == 0 && ok) {
            sx[img][grp * 4 + 0] = q0; sx[img][grp * 4 + 1] = q1;
            sx[img][grp * 4 + 2] = q2; sx[img][grp * 4 + 3] = q3;
        }
    }
    __syncthreads();

    // ---- stage 2: conv1 + pool + binarize, BITSLICED over 28 ox ----
    // thread = (img, py, cr). Window count(ox) for all 28 ox computed as
    // bitplanes via a 25-input Wallace counter; threshold <=12 bitsliced.
    if (tid < imax * 28) {
        int img = tid / 28, r = tid % 28;
        int py = r >> 1, cr = r & 1;

        unsigned pl[25];  // pl[5j+i]: bit ox = inputrow(2py+cr+j) bit (ox+i)
#pragma unroll
        for (int j = 0; j < 5; j++) {
            unsigned rv = sx[img][2 * py + cr + j];
#pragma unroll
            for (int i = 0; i < 5; i++) pl[5 * j + i] = rv >> i;
        }

#pragma unroll
        for (int oc = 0; oc < 6; oc++) {
            const unsigned* wm = &swm1[oc * 25];
            unsigned xk[25];
#pragma unroll
            for (int t = 0; t < 25; t++) xk[t] = pl[t] ^ wm[t];

            // Wallace 25 -> 5 bitplanes (b0..b4), 20 FA + 2 HA
            unsigned s1[8], c1[8];
#pragma unroll
            for (int k = 0; k < 8; k++)
                csa(s1[k], c1[k], xk[3 * k], xk[3 * k + 1], xk[3 * k + 2]);
            unsigned s2[3], c2[3];
            csa(s2[0], c2[0], s1[0], s1[1], s1[2]);
            csa(s2[1], c2[1], s1[3], s1[4], s1[5]);
            csa(s2[2], c2[2], s1[6], s1[7], xk[24]);
            unsigned b0v, c3v;
            csa(b0v, c3v, s2[0], s2[1], s2[2]);          // b0v = bit0
            unsigned s4[4], c4a[4];
            csa(s4[0], c4a[0], c1[0], c1[1], c1[2]);
            csa(s4[1], c4a[1], c1[3], c1[4], c1[5]);
            csa(s4[2], c4a[2], c1[6], c1[7], c2[0]);
            csa(s4[3], c4a[3], c2[1], c2[2], c3v);
            unsigned s5, c5;
            csa(s5, c5, s4[0], s4[1], s4[2]);
            unsigned b1v = s5 ^ s4[3];                   // bit1
            unsigned c6 = s5 & s4[3];
            unsigned s7a, c7a, s7b, c7b;
            csa(s7a, c7a, c4a[0], c4a[1], c4a[2]);
            csa(s7b, c7b, c4a[3], c5, c6);
            unsigned b2v = s7a ^ s7b;                    // bit2
            unsigned c8 = s7a & s7b;
            unsigned b3v, b4v;
            csa(b3v, b4v, c7a, c7b, c8);                 // bit3, bit4

            // count <= 12  <=>  !(b4 | (b3 & b2 & (b1 | b0)))
            unsigned t1 = b1v | b0v;
            unsigned t2 = b3v & b2v & t1;
            unsigned m = ~(b4v | t2);                    // sign mask over ox 0..27

            m |= __shfl_xor_sync(0xffffffffu, m, 1);     // merge cr=0/1
            if (cr == 0) {
                unsigned v = (m | (m >> 1)) & 0x55555555u;   // horizontal pool
                v = (v | (v >> 1)) & 0x33333333u;            // compact even bits
                v = (v | (v >> 2)) & 0x0F0F0F0Fu;
                v = (v | (v >> 4)) & 0x00FF00FFu;
                v = ((v | (v >> 8)) & 0x0000FFFFu) & 0x3FFFu;
                sc1[img][py][oc] = v;
            }
        }
    }
    __syncthreads();

    // ---- stage 3: conv2 + pool + ternarize (IPB*25 = 200 cells) ----
    if (tid < imax * 25) {
        int img = tid / 25, cell = tid % 25;
        int py = cell / 5, px = cell % 5;
        int ox0 = 2 * px;

        unsigned wpk[4][5];
#pragma unroll
        for (int q = 0; q < 4; q++)
#pragma unroll
            for (int w = 0; w < 5; w++) wpk[q][w] = 0u;

#pragma unroll
        for (int icp = 0; icp < 3; icp++) {
            unsigned ra[6], rb[6];
#pragma unroll
            for (int k = 0; k < 6; k++) {
                uint2 v = *(const uint2*)&sc1[img][2 * py + k][icp * 2];
                ra[k] = v.x; rb[k] = v.y;
            }
#pragma unroll
            for (int h = 0; h < 2; h++) {
                int ox = ox0 + h;
                unsigned va0 = 0, vb0 = 0;
#pragma unroll
                for (int j = 0; j < 5; j++) {
                    va0 |= ((ra[j] >> ox) & 31u) << (5 * j);
                    vb0 |= ((rb[j] >> ox) & 31u) << (5 * j);
                }
                unsigned va1 = (va0 >> 5) | (((ra[5] >> ox) & 31u) << 20);
                unsigned vb1 = (vb0 >> 5) | (((rb[5] >> ox) & 31u) << 20);
                if (icp == 0) {
                    wpk[h][0]     |= va0 | (vb0 << 25);
                    wpk[h][1]     |= vb0 >> 7;
                    wpk[2 + h][0] |= va1 | (vb1 << 25);
                    wpk[2 + h][1] |= vb1 >> 7;
                } else if (icp == 1) {
                    wpk[h][1]     |= va0 << 18;
                    wpk[h][2]     |= (va0 >> 14) | (vb0 << 11);
                    wpk[h][3]     |= vb0 >> 21;
                    wpk[2 + h][1] |= va1 << 18;
                    wpk[2 + h][2] |= (va1 >> 14) | (vb1 << 11);
                    wpk[2 + h][3] |= vb1 >> 21;
                } else {
                    wpk[h][3]     |= (va0 << 4) | (vb0 << 29);
                    wpk[h][4]     |= vb0 >> 3;
                    wpk[2 + h][3] |= (va1 << 4) | (vb1 << 29);
                    wpk[2 + h][4] |= vb1 >> 3;
                }
            }
        }

        unsigned word = 0;
        uint4 wa = sw4[0][0];
        unsigned w4v = sw4[0][1].x;
#pragma unroll
        for (int oc = 0; oc < 16; oc++) {
            uint4 wan;
            unsigned w4n;
            if (oc < 15) { wan = sw4[oc + 1][0]; w4n = sw4[oc + 1][1].x; }
            int d[4];
#pragma unroll
            for (int q = 0; q < 4; q++) {
                unsigned x0 = wpk[q][0] ^ wa.x;
                unsigned x1 = wpk[q][1] ^ wa.y;
                unsigned x2 = wpk[q][2] ^ wa.z;
                unsigned x3 = wpk[q][3] ^ wa.w;
                unsigned x4 = wpk[q][4] ^ w4v;
                unsigned sA, cA, sB, cB;
                csa(sA, cA, x0, x1, x2);
                csa(sB, cB, sA, x3, x4);
                d[q] = __popc(sB) + 2 * (__popc(cA) + __popc(cB));
            }
            int m = min(min(d[0], d[1]), min(d[2], d[3]));
            if (m <= 74) word |= 1u << oc;
            if (m != 75) word |= 1u << (16 + oc);
            if (oc < 15) { wa = wan; w4v = w4n; }
        }
        ss2[img][cell] = word;
    }
    __syncthreads();

    // ---- stage 4: fc1 -> fc2 -> fc3, one warp per image ----
    {
        int img = warp;
        if (img < imax) {
            unsigned W = (lane < 25) ? ss2[img][lane] : 0u;
            unsigned sp[16], sm[16];
#pragma unroll
            for (int oc = 0; oc < 16; oc++) {
                sp[oc] = __ballot_sync(0xffffffffu, (W >> oc) & 1u);
                sm[oc] = __ballot_sync(0xffffffffu, (W >> (16 + oc)) & 1u);
            }
            int M1;
            {
                unsigned sA, cA, sB, cB, sC, cC, sD, cD;
                csa(sA, cA, sm[0], sm[1], sm[2]);
                csa(sB, cB, sm[3], sm[4], sm[5]);
                csa(sC, cC, sA, sB, sm[6]);
                csa(sD, cD, cA, cB, cC);
                M1 = __popc(sC) + __popc(sm[7]) + 2 * __popc(sD) + 4 * __popc(cD);
                csa(sA, cA, sm[8], sm[9], sm[10]);
                csa(sB, cB, sm[11], sm[12], sm[13]);
                csa(sC, cC, sA, sB, sm[14]);
                csa(sD, cD, cA, cB, cC);
                M1 += __popc(sC) + __popc(sm[15]) + 2 * __popc(sD) + 4 * __popc(cD);
            }

            unsigned p2s[4], p2m[4];
#pragma unroll
            for (int k = 0; k < 4; k++) {
                int n = k * 32 + lane;
                int v = 0;
                bool valid = (n < 120);
                if (valid) {
                    unsigned t[16];
#pragma unroll
                    for (int i = 0; i < 16; i++)
                        t[i] = (~(sp[i] ^ s1w[n * 17 + i])) & sm[i];
                    unsigned sA, cA, sB, cB, sC, cC, sD, cD;
                    csa(sA, cA, t[0], t[1], t[2]);
                    csa(sB, cB, t[3], t[4], t[5]);
                    csa(sC, cC, sA, sB, t[6]);
                    csa(sD, cD, cA, cB, cC);
                    int p = __popc(sC) + __popc(t[7]) + 2 * __popc(sD) + 4 * __popc(cD);
                    csa(sA, cA, t[8], t[9], t[10]);
                    csa(sB, cB, t[11], t[12], t[13]);
                    csa(sC, cC, sA, sB, t[14]);
                    csa(sD, cD, cA, cB, cC);
                    p += __popc(sC) + __popc(t[15]) + 2 * __popc(sD) + 4 * __popc(cD);
                    v = 2 * p - M1;
                }
                p2s[k] = __ballot_sync(0xffffffffu, valid && (v > 0));
                p2m[k] = __ballot_sync(0xffffffffu, valid && (v != 0));
            }
            int M2;
            {
                unsigned s, c;
                csa(s, c, p2m[0], p2m[1], p2m[2]);
                M2 = __popc(s) + __popc(p2m[3]) + 2 * __popc(c);
            }

            unsigned p3s[3], p3m[3];
#pragma unroll
            for (int k = 0; k < 3; k++) {
                int n = k * 32 + lane;
                int v = 0;
                bool valid = (n < 84);
                if (valid) {
                    unsigned t0 = (~(p2s[0] ^ s2w[n * 5 + 0])) & p2m[0];
                    unsigned t1 = (~(p2s[1] ^ s2w[n * 5 + 1])) & p2m[1];
                    unsigned t2 = (~(p2s[2] ^ s2w[n * 5 + 2])) & p2m[2];
                    unsigned t3 = (~(p2s[3] ^ s2w[n * 5 + 3])) & p2m[3];
                    unsigned s, c;
                    csa(s, c, t0, t1, t2);
                    int p = __popc(s) + __popc(t3) + 2 * __popc(c);
                    v = 2 * p - M2;
                }
                p3s[k] = __ballot_sync(0xffffffffu, valid && (v > 0));
                p3m[k] = __ballot_sync(0xffffffffu, valid && (v != 0));
            }
            int M3;
            {
                unsigned s, c;
                csa(s, c, p3m[0], p3m[1], p3m[2]);
                M3 = __popc(s) + 2 * __popc(c);
            }

            if (lane < 10) {
                unsigned t0 = (~(p3s[0] ^ s3w[lane * 3 + 0])) & p3m[0];
                unsigned t1 = (~(p3s[1] ^ s3w[lane * 3 + 1])) & p3m[1];
                unsigned t2 = (~(p3s[2] ^ s3w[lane * 3 + 2])) & p3m[2];
                unsigned s, c;
                csa(s, c, t0, t1, t2);
                int p = __popc(s) + 2 * __popc(c);
                out[(size_t)(b0 + img) * 10 + lane] = (float)(2 * p - M3);
            }
        }
    }
}

// ---------------- launch ----------------
extern "C" void kernel_launch(void* const* d_in, const int* in_sizes, int n_in,
                              void* d_out, int out_size) {
    const float* x  = (const float*)d_in[0];
    const float* w1 = (const float*)d_in[1];
    const float* w2 = (const float*)d_in[2];
    const float* f1 = (const float*)d_in[3];
    const float* f2 = (const float*)d_in[4];
    const float* f3 = (const float*)d_in[5];
    float* out = (float*)d_out;

    int B = in_sizes[0] / 1024;
    if (B > B_MAX) B = B_MAX;

    pack_weights<<<32, 256>>>(w1, w2, f1, f2, f3);

    int blocks = (B + IPB - 1) / IPB;
    mega_k<<<blocks, 256>>>(x, out, B);
}

// round 16
// speedup vs baseline: 1.2948x; 1.0602x over previous
#include <cuda_runtime.h>
#include <stdint.h>

#define B_MAX 16384
#define IPB 8   // images per block

__device__ __forceinline__ void csa(unsigned& s, unsigned& c,
                                    unsigned a, unsigned b, unsigned d) {
    s = a ^ b ^ d;                      // LOP3 0x96
    c = (a & b) | (d & (a ^ b));        // LOP3 0xE8 (majority)
}

// ---------------- weight scratch (device globals) ----------------
__device__ unsigned g_wm1[6 * 25];    // conv1 weight sign BROADCAST masks (0 / ~0)
__device__ unsigned g_wp2[16 * 8];    // conv2 weights packed 150b -> 5 words, pad 8
__device__ unsigned g_fw1[120 * 16];  // fc1: 25-bit word per (n, oc)
__device__ unsigned g_fw2[84 * 4];    // fc2: 120 bits -> 4 words per n
__device__ unsigned g_fw3[10 * 3];    // fc3: 84 bits -> 3 words per n

// ---------------- K0: pack all weights, warp-per-word (ballot) -----------
// fc1: 1920 warps | fc2: 336 | fc3: 30 | conv2: 16 | conv1 masks: 5
__global__ void pack_weights(const float* __restrict__ w1, const float* __restrict__ w2,
                             const float* __restrict__ f1, const float* __restrict__ f2,
                             const float* __restrict__ f3) {
    int gw = (blockIdx.x * blockDim.x + threadIdx.x) >> 5;
    int lane = threadIdx.x & 31;

    if (gw < 1920) {                       // fc1 word (n, oc)
        int n = gw >> 4, oc = gw & 15;
        float v = (lane < 25) ? f1[n * 400 + oc * 25 + lane] : 0.f;
        unsigned b = __ballot_sync(0xffffffffu, (lane < 25) && (v > 0.f));
        if (lane == 0) g_fw1[gw] = b;
    } else if (gw < 2256) {                // fc2 word (n, j)
        int w = gw - 1920;
        int n = w >> 2, j = w & 3;
        int i = j * 32 + lane;
        float v = (i < 120) ? f2[n * 120 + i] : 0.f;
        unsigned b = __ballot_sync(0xffffffffu, (i < 120) && (v > 0.f));
        if (lane == 0) g_fw2[w] = b;
    } else if (gw < 2286) {                // fc3 word (n, j)
        int w = gw - 2256;
        int n = w / 3, j = w % 3;
        int i = j * 32 + lane;
        float v = (i < 84) ? f3[n * 84 + i] : 0.f;
        unsigned b = __ballot_sync(0xffffffffu, (i < 84) && (v > 0.f));
        if (lane == 0) g_fw3[w] = b;
    } else if (gw < 2302) {                // conv2: warp per oc
        int oc = gw - 2286;
        unsigned wi[6];
#pragma unroll
        for (int ic = 0; ic < 6; ic++) {
            float v = (lane < 25) ? w2[(oc * 6 + ic) * 25 + lane] : 0.f;
            wi[ic] = __ballot_sync(0xffffffffu, (lane < 25) && (v > 0.f));
        }
        if (lane == 0) {
            g_wp2[oc * 8 + 0] = wi[0] | (wi[1] << 25);
            g_wp2[oc * 8 + 1] = (wi[1] >> 7) | (wi[2] << 18);
            g_wp2[oc * 8 + 2] = (wi[2] >> 14) | (wi[3] << 11);
            g_wp2[oc * 8 + 3] = (wi[3] >> 21) | (wi[4] << 4) | (wi[5] << 29);
            g_wp2[oc * 8 + 4] = (wi[5] >> 3);
            g_wp2[oc * 8 + 5] = 0; g_wp2[oc * 8 + 6] = 0; g_wp2[oc * 8 + 7] = 0;
        }
    } else {                               // conv1 broadcast masks (150)
        int t = (gw - 2302) * 32 + lane;
        if (t < 150) g_wm1[t] = (w1[t] > 0.f) ? 0xffffffffu : 0u;
    }
}

// ---------------- mega kernel: pack -> conv1(bitsliced) -> conv2 -> fc ---
__global__ void __launch_bounds__(256, 4) mega_k(const float* __restrict__ x,
                                                 float* __restrict__ out, int B) {
    __shared__ unsigned sx[IPB][32];
    __shared__ __align__(16) unsigned sc1[IPB][14][6];
    __shared__ unsigned ss2[IPB][25];
    __shared__ unsigned s1w[120 * 17];
    __shared__ unsigned s2w[84 * 5];
    __shared__ unsigned s3w[30];
    __shared__ unsigned swm1[6 * 25];
    __shared__ uint4 sw4[16][2];

    int tid = threadIdx.x, warp = tid >> 5, lane = tid & 31;
    int b0 = blockIdx.x * IPB;
    int imax = B - b0; if (imax > IPB) imax = IPB;

    // ---- load weights into smem ----
    for (int i = tid; i < 120 * 16; i += 256) s1w[(i >> 4) * 17 + (i & 15)] = g_fw1[i];
    for (int i = tid; i < 84 * 4; i += 256) s2w[(i >> 2) * 5 + (i & 3)] = g_fw2[i];
    if (tid < 30) s3w[tid] = g_fw3[tid];
    if (tid < 150) swm1[tid] = g_wm1[tid];
    if (tid >= 160 && tid < 192) {
        int k = tid - 160;
        sw4[k >> 1][k & 1] = ((const uint4*)&g_wp2[(k >> 1) * 8])[k & 1];
    }

    // ---- stage 1: pack x signs ----
#pragma unroll
    for (int it = 0; it < IPB; it++) {
        int g = warp + it * 8;
        int img = g >> 3, grp = g & 7;
        bool ok = (img < imax);
        const float* p = x + (size_t)(b0 + img) * 1024 + grp * 128 + lane;
        float v0 = ok ? p[0]  : 0.f;
        float v1 = ok ? p[32] : 0.f;
        float v2 = ok ? p[64] : 0.f;
        float v3 = ok ? p[96] : 0.f;
        unsigned q0 = __ballot_sync(0xffffffffu, v0 > 0.f);
        unsigned q1 = __ballot_sync(0xffffffffu, v1 > 0.f);
        unsigned q2 = __ballot_sync(0xffffffffu, v2 > 0.f);
        unsigned q3 = __ballot_sync(0xffffffffu, v3 > 0.f);
        if (lane == 0 && ok) {
            sx[img][grp * 4 + 0] = q0; sx[img][grp * 4 + 1] = q1;
            sx[img][grp * 4 + 2] = q2; sx[img][grp * 4 + 3] = q3;
        }
    }
    __syncthreads();

    // ---- stage 2: conv1 + pool + binarize, BITSLICED over 28 ox ----
    if (tid < imax * 28) {
        int img = tid / 28, r = tid % 28;
        int py = r >> 1, cr = r & 1;

        unsigned pl[25];  // pl[5j+i]: bit ox = inputrow(2py+cr+j) bit (ox+i)
#pragma unroll
        for (int j = 0; j < 5; j++) {
            unsigned rv = sx[img][2 * py + cr + j];
#pragma unroll
            for (int i = 0; i < 5; i++) pl[5 * j + i] = rv >> i;
        }

        unsigned vout[6];
#pragma unroll
        for (int oc = 0; oc < 6; oc++) {
            const unsigned* wm = &swm1[oc * 25];
            unsigned xk[25];
#pragma unroll
            for (int t = 0; t < 25; t++) xk[t] = pl[t] ^ wm[t];

            // Wallace 25 -> 5 bitplanes (b0..b4)
            unsigned s1[8], c1[8];
#pragma unroll
            for (int k = 0; k < 8; k++)
                csa(s1[k], c1[k], xk[3 * k], xk[3 * k + 1], xk[3 * k + 2]);
            unsigned s2[3], c2[3];
            csa(s2[0], c2[0], s1[0], s1[1], s1[2]);
            csa(s2[1], c2[1], s1[3], s1[4], s1[5]);
            csa(s2[2], c2[2], s1[6], s1[7], xk[24]);
            unsigned b0v, c3v;
            csa(b0v, c3v, s2[0], s2[1], s2[2]);
            unsigned s4[4], c4a[4];
            csa(s4[0], c4a[0], c1[0], c1[1], c1[2]);
            csa(s4[1], c4a[1], c1[3], c1[4], c1[5]);
            csa(s4[2], c4a[2], c1[6], c1[7], c2[0]);
            csa(s4[3], c4a[3], c2[1], c2[2], c3v);
            unsigned s5, c5;
            csa(s5, c5, s4[0], s4[1], s4[2]);
            unsigned b1v = s5 ^ s4[3];
            unsigned c6 = s5 & s4[3];
            unsigned s7a, c7a, s7b, c7b;
            csa(s7a, c7a, c4a[0], c4a[1], c4a[2]);
            csa(s7b, c7b, c4a[3], c5, c6);
            unsigned b2v = s7a ^ s7b;
            unsigned c8 = s7a & s7b;
            unsigned b3v, b4v;
            csa(b3v, b4v, c7a, c7b, c8);

            // count <= 12  <=>  !(b4 | (b3 & b2 & (b1 | b0)))
            unsigned t1 = b1v | b0v;
            unsigned t2 = b3v & b2v & t1;
            unsigned m = ~(b4v | t2);

            m |= __shfl_xor_sync(0xffffffffu, m, 1);     // merge cr=0/1
            unsigned v = (m | (m >> 1)) & 0x55555555u;   // horizontal pool
            v = (v | (v >> 1)) & 0x33333333u;            // compact even bits
            v = (v | (v >> 2)) & 0x0F0F0F0Fu;
            v = (v | (v >> 4)) & 0x00FF00FFu;
            v = ((v | (v >> 8)) & 0x0000FFFFu) & 0x3FFFu;
            vout[oc] = v;
        }
        if (cr == 0) {
            uint2* dst = (uint2*)&sc1[img][py][0];
            dst[0] = make_uint2(vout[0], vout[1]);
            dst[1] = make_uint2(vout[2], vout[3]);
            dst[2] = make_uint2(vout[4], vout[5]);
        }
    }
    __syncthreads();

    // ---- stage 3: conv2 + pool + ternarize (IPB*25 = 200 cells) ----
    if (tid < imax * 25) {
        int img = tid / 25, cell = tid % 25;
        int py = cell / 5, px = cell % 5;
        int ox0 = 2 * px;

        unsigned wpk[4][5];
#pragma unroll
        for (int q = 0; q < 4; q++)
#pragma unroll
            for (int w = 0; w < 5; w++) wpk[q][w] = 0u;

#pragma unroll
        for (int icp = 0; icp < 3; icp++) {
            unsigned ra[6], rb[6];
#pragma unroll
            for (int k = 0; k < 6; k++) {
                uint2 v = *(const uint2*)&sc1[img][2 * py + k][icp * 2];
                ra[k] = v.x; rb[k] = v.y;
            }
#pragma unroll
            for (int h = 0; h < 2; h++) {
                int ox = ox0 + h;
                unsigned va0 = 0, vb0 = 0;
#pragma unroll
                for (int j = 0; j < 5; j++) {
                    va0 |= ((ra[j] >> ox) & 31u) << (5 * j);
                    vb0 |= ((rb[j] >> ox) & 31u) << (5 * j);
                }
                unsigned va1 = (va0 >> 5) | (((ra[5] >> ox) & 31u) << 20);
                unsigned vb1 = (vb0 >> 5) | (((rb[5] >> ox) & 31u) << 20);
                if (icp == 0) {
                    wpk[h][0]     |= va0 | (vb0 << 25);
                    wpk[h][1]     |= vb0 >> 7;
                    wpk[2 + h][0] |= va1 | (vb1 << 25);
                    wpk[2 + h][1] |= vb1 >> 7;
                } else if (icp == 1) {
                    wpk[h][1]     |= va0 << 18;
                    wpk[h][2]     |= (va0 >> 14) | (vb0 << 11);
                    wpk[h][3]     |= vb0 >> 21;
                    wpk[2 + h][1] |= va1 << 18;
                    wpk[2 + h][2] |= (va1 >> 14) | (vb1 << 11);
                    wpk[2 + h][3] |= vb1 >> 21;
                } else {
                    wpk[h][3]     |= (va0 << 4) | (vb0 << 29);
                    wpk[h][4]     |= vb0 >> 3;
                    wpk[2 + h][3] |= (va1 << 4) | (vb1 << 29);
                    wpk[2 + h][4] |= vb1 >> 3;
                }
            }
        }

        unsigned word = 0;
        uint4 wa = sw4[0][0];
        unsigned w4v = sw4[0][1].x;
#pragma unroll
        for (int oc = 0; oc < 16; oc++) {
            uint4 wan;
            unsigned w4n;
            if (oc < 15) { wan = sw4[oc + 1][0]; w4n = sw4[oc + 1][1].x; }
            int d[4];
#pragma unroll
            for (int q = 0; q < 4; q++) {
                unsigned x0 = wpk[q][0] ^ wa.x;
                unsigned x1 = wpk[q][1] ^ wa.y;
                unsigned x2 = wpk[q][2] ^ wa.z;
                unsigned x3 = wpk[q][3] ^ wa.w;
                unsigned x4 = wpk[q][4] ^ w4v;
                unsigned sA, cA, sB, cB;
                csa(sA, cA, x0, x1, x2);
                csa(sB, cB, sA, x3, x4);
                d[q] = __popc(sB) + 2 * (__popc(cA) + __popc(cB));
            }
            int m = min(min(d[0], d[1]), min(d[2], d[3]));
            if (m <= 74) word |= 1u << oc;
            if (m != 75) word |= 1u << (16 + oc);
            if (oc < 15) { wa = wan; w4v = w4n; }
        }
        ss2[img][cell] = word;
    }
    __syncthreads();

    // ---- stage 4: fc1 -> fc2 -> fc3, one warp per image ----
    {
        int img = warp;
        if (img < imax) {
            unsigned W = (lane < 25) ? ss2[img][lane] : 0u;
            unsigned sp[16], sm[16];
#pragma unroll
            for (int oc = 0; oc < 16; oc++) {
                sp[oc] = __ballot_sync(0xffffffffu, (W >> oc) & 1u);
                sm[oc] = __ballot_sync(0xffffffffu, (W >> (16 + oc)) & 1u);
            }
            int M1;
            {
                unsigned sA, cA, sB, cB, sC, cC, sD, cD;
                csa(sA, cA, sm[0], sm[1], sm[2]);
                csa(sB, cB, sm[3], sm[4], sm[5]);
                csa(sC, cC, sA, sB, sm[6]);
                csa(sD, cD, cA, cB, cC);
                M1 = __popc(sC) + __popc(sm[7]) + 2 * __popc(sD) + 4 * __popc(cD);
                csa(sA, cA, sm[8], sm[9], sm[10]);
                csa(sB, cB, sm[11], sm[12], sm[13]);
                csa(sC, cC, sA, sB, sm[14]);
                csa(sD, cD, cA, cB, cC);
                M1 += __popc(sC) + __popc(sm[15]) + 2 * __popc(sD) + 4 * __popc(cD);
            }

            unsigned p2s[4], p2m[4];
#pragma unroll
            for (int k = 0; k < 4; k++) {
                int n = k * 32 + lane;
                int v = 0;
                bool valid = (n < 120);
                if (valid) {
                    unsigned t[16];
#pragma unroll
                    for (int i = 0; i < 16; i++)
                        t[i] = (~(sp[i] ^ s1w[n * 17 + i])) & sm[i];
                    unsigned sA, cA, sB, cB, sC, cC, sD, cD;
                    csa(sA, cA, t[0], t[1], t[2]);
                    csa(sB, cB, t[3], t[4], t[5]);
                    csa(sC, cC, sA, sB, t[6]);
                    csa(sD, cD, cA, cB, cC);
                    int p = __popc(sC) + __popc(t[7]) + 2 * __popc(sD) + 4 * __popc(cD);
                    csa(sA, cA, t[8], t[9], t[10]);
                    csa(sB, cB, t[11], t[12], t[13]);
                    csa(sC, cC, sA, sB, t[14]);
                    csa(sD, cD, cA, cB, cC);
                    p += __popc(sC) + __popc(t[15]) + 2 * __popc(sD) + 4 * __popc(cD);
                    v = 2 * p - M1;
                }
                p2s[k] = __ballot_sync(0xffffffffu, valid && (v > 0));
                p2m[k] = __ballot_sync(0xffffffffu, valid && (v != 0));
            }
            int M2;
            {
                unsigned s, c;
                csa(s, c, p2m[0], p2m[1], p2m[2]);
                M2 = __popc(s) + __popc(p2m[3]) + 2 * __popc(c);
            }

            unsigned p3s[3], p3m[3];
#pragma unroll
            for (int k = 0; k < 3; k++) {
                int n = k * 32 + lane;
                int v = 0;
                bool valid = (n < 84);
                if (valid) {
                    unsigned t0 = (~(p2s[0] ^ s2w[n * 5 + 0])) & p2m[0];
                    unsigned t1 = (~(p2s[1] ^ s2w[n * 5 + 1])) & p2m[1];
                    unsigned t2 = (~(p2s[2] ^ s2w[n * 5 + 2])) & p2m[2];
                    unsigned t3 = (~(p2s[3] ^ s2w[n * 5 + 3])) & p2m[3];
                    unsigned s, c;
                    csa(s, c, t0, t1, t2);
                    int p = __popc(s) + __popc(t3) + 2 * __popc(c);
                    v = 2 * p - M2;
                }
                p3s[k] = __ballot_sync(0xffffffffu, valid && (v > 0));
                p3m[k] = __ballot_sync(0xffffffffu, valid && (v != 0));
            }
            int M3;
            {
                unsigned s, c;
                csa(s, c, p3m[0], p3m[1], p3m[2]);
                M3 = __popc(s) + 2 * __popc(c);
            }

            if (lane < 10) {
                unsigned t0 = (~(p3s[0] ^ s3w[lane * 3 + 0])) & p3m[0];
                unsigned t1 = (~(p3s[1] ^ s3w[lane * 3 + 1])) & p3m[1];
                unsigned t2 = (~(p3s[2] ^ s3w[lane * 3 + 2])) & p3m[2];
                unsigned s, c;
                csa(s, c, t0, t1, t2);
                int p = __popc(s) + 2 * __popc(c);
                out[(size_t)(b0 + img) * 10 + lane] = (float)(2 * p - M3);
            }
        }
    }
}

// ---------------- launch ----------------
extern "C" void kernel_launch(void* const* d_in, const int* in_sizes, int n_in,
                              void* d_out, int out_size) {
    const float* x  = (const float*)d_in[0];
    const float* w1 = (const float*)d_in[1];
    const float* w2 = (const float*)d_in[2];
    const float* f1 = (const float*)d_in[3];
    const float* f2 = (const float*)d_in[4];
    const float* f3 = (const float*)d_in[5];
    float* out = (float*)d_out;

    int B = in_sizes[0] / 1024;
    if (B > B_MAX) B = B_MAX;

    // 2307 warps needed -> 289 blocks of 256 (8 warps each)
    pack_weights<<<289, 256>>>(w1, w2, f1, f2, f3);

    int blocks = (B + IPB - 1) / IPB;
    mega_k<<<blocks, 256>>>(x, out, B);
}

// round 17
// speedup vs baseline: 1.3292x; 1.0265x over previous
#include <cuda_runtime.h>
#include <stdint.h>

#define B_MAX 16384
#define IPB 8   // images per block

__device__ __forceinline__ void csa(unsigned& s, unsigned& c,
                                    unsigned a, unsigned b, unsigned d) {
    s = a ^ b ^ d;                      // LOP3 0x96
    c = (a & b) | (d & (a ^ b));        // LOP3 0xE8 (majority)
}

// ---------------- weight scratch (device globals) ----------------
__device__ unsigned g_wm1[6 * 25];    // conv1 weight sign BROADCAST masks (0 / ~0)
__device__ unsigned g_wp2[16 * 8];    // conv2 weights packed 150b -> 5 words, pad 8
__device__ unsigned g_fw1[120 * 16];  // fc1: 25-bit word per (n, oc)
__device__ unsigned g_fw2[84 * 4];    // fc2: 120 bits -> 4 words per n
__device__ unsigned g_fw3[10 * 3];    // fc3: 84 bits -> 3 words per n

// ---------------- K0: pack all weights, warp-per-word (ballot) -----------
__global__ void pack_weights(const float* __restrict__ w1, const float* __restrict__ w2,
                             const float* __restrict__ f1, const float* __restrict__ f2,
                             const float* __restrict__ f3) {
    int gw = (blockIdx.x * blockDim.x + threadIdx.x) >> 5;
    int lane = threadIdx.x & 31;

    if (gw < 1920) {                       // fc1 word (n, oc)
        int n = gw >> 4, oc = gw & 15;
        float v = (lane < 25) ? f1[n * 400 + oc * 25 + lane] : 0.f;
        unsigned b = __ballot_sync(0xffffffffu, (lane < 25) && (v > 0.f));
        if (lane == 0) g_fw1[gw] = b;
    } else if (gw < 2256) {                // fc2 word (n, j)
        int w = gw - 1920;
        int n = w >> 2, j = w & 3;
        int i = j * 32 + lane;
        float v = (i < 120) ? f2[n * 120 + i] : 0.f;
        unsigned b = __ballot_sync(0xffffffffu, (i < 120) && (v > 0.f));
        if (lane == 0) g_fw2[w] = b;
    } else if (gw < 2286) {                // fc3 word (n, j)
        int w = gw - 2256;
        int n = w / 3, j = w % 3;
        int i = j * 32 + lane;
        float v = (i < 84) ? f3[n * 84 + i] : 0.f;
        unsigned b = __ballot_sync(0xffffffffu, (i < 84) && (v > 0.f));
        if (lane == 0) g_fw3[w] = b;
    } else if (gw < 2302) {                // conv2: warp per oc
        int oc = gw - 2286;
        unsigned wi[6];
#pragma unroll
        for (int ic = 0; ic < 6; ic++) {
            float v = (lane < 25) ? w2[(oc * 6 + ic) * 25 + lane] : 0.f;
            wi[ic] = __ballot_sync(0xffffffffu, (lane < 25) && (v > 0.f));
        }
        if (lane == 0) {
            g_wp2[oc * 8 + 0] = wi[0] | (wi[1] << 25);
            g_wp2[oc * 8 + 1] = (wi[1] >> 7) | (wi[2] << 18);
            g_wp2[oc * 8 + 2] = (wi[2] >> 14) | (wi[3] << 11);
            g_wp2[oc * 8 + 3] = (wi[3] >> 21) | (wi[4] << 4) | (wi[5] << 29);
            g_wp2[oc * 8 + 4] = (wi[5] >> 3);
            g_wp2[oc * 8 + 5] = 0; g_wp2[oc * 8 + 6] = 0; g_wp2[oc * 8 + 7] = 0;
        }
    } else {                               // conv1 broadcast masks (150)
        int t = (gw - 2302) * 32 + lane;
        if (t < 150) g_wm1[t] = (w1[t] > 0.f) ? 0xffffffffu : 0u;
    }
}

// ---------------- mega kernel: pack -> conv1(bitsliced) -> conv2 -> fc ---
__global__ void __launch_bounds__(256, 5) mega_k(const float* __restrict__ x,
                                                 float* __restrict__ out, int B) {
    __shared__ unsigned sx[IPB][32];
    __shared__ __align__(16) unsigned sc1[IPB][14][6];
    __shared__ unsigned ss2[IPB][25];
    __shared__ unsigned s1w[120 * 17];
    __shared__ unsigned s2w[84 * 5];
    __shared__ unsigned s3w[30];
    __shared__ unsigned swm1[6 * 25];
    __shared__ uint4 sw4[16][2];

    int tid = threadIdx.x, warp = tid >> 5, lane = tid & 31;
    int b0 = blockIdx.x * IPB;
    int imax = B - b0; if (imax > IPB) imax = IPB;

    // ---- load weights into smem ----
    for (int i = tid; i < 120 * 16; i += 256) s1w[(i >> 4) * 17 + (i & 15)] = g_fw1[i];
    for (int i = tid; i < 84 * 4; i += 256) s2w[(i >> 2) * 5 + (i & 3)] = g_fw2[i];
    if (tid < 30) s3w[tid] = g_fw3[tid];
    if (tid < 150) swm1[tid] = g_wm1[tid];
    if (tid >= 160 && tid < 192) {
        int k = tid - 160;
        sw4[k >> 1][k & 1] = ((const uint4*)&g_wp2[(k >> 1) * 8])[k & 1];
    }

    // ---- stage 1: pack x signs ----
#pragma unroll
    for (int it = 0; it < IPB; it++) {
        int g = warp + it * 8;
        int img = g >> 3, grp = g & 7;
        bool ok = (img < imax);
        const float* p = x + (size_t)(b0 + img) * 1024 + grp * 128 + lane;
        float v0 = ok ? p[0]  : 0.f;
        float v1 = ok ? p[32] : 0.f;
        float v2 = ok ? p[64] : 0.f;
        float v3 = ok ? p[96] : 0.f;
        unsigned q0 = __ballot_sync(0xffffffffu, v0 > 0.f);
        unsigned q1 = __ballot_sync(0xffffffffu, v1 > 0.f);
        unsigned q2 = __ballot_sync(0xffffffffu, v2 > 0.f);
        unsigned q3 = __ballot_sync(0xffffffffu, v3 > 0.f);
        if (lane == 0 && ok) {
            sx[img][grp * 4 + 0] = q0; sx[img][grp * 4 + 1] = q1;
            sx[img][grp * 4 + 2] = q2; sx[img][grp * 4 + 3] = q3;
        }
    }
    __syncthreads();

    // ---- stage 2: conv1 + pool + binarize, BITSLICED over 28 ox ----
    // Register-diet version: oc loop NOT unrolled; xk streamed inline from
    // 6 row registers (no pl[25]/xk[25] arrays) to stay within 51 regs.
    if (tid < imax * 28) {
        int img = tid / 28, r = tid % 28;
        int py = r >> 1, cr = r & 1;

        unsigned rv[6];
#pragma unroll
        for (int k = 0; k < 6; k++) rv[k] = sx[img][2 * py + cr + k];

#pragma unroll 1
        for (int oc = 0; oc < 6; oc++) {
            const unsigned* wm = &swm1[oc * 25];

            unsigned s1[8], c1[8];
#pragma unroll
            for (int k = 0; k < 8; k++) {
                int t0 = 3 * k, t1 = 3 * k + 1, t2 = 3 * k + 2;
                unsigned a = (rv[t0 / 5] >> (t0 % 5)) ^ wm[t0];
                unsigned b = (rv[t1 / 5] >> (t1 % 5)) ^ wm[t1];
                unsigned d = (rv[t2 / 5] >> (t2 % 5)) ^ wm[t2];
                csa(s1[k], c1[k], a, b, d);
            }
            unsigned xk24 = (rv[4] >> 4) ^ wm[24];

            unsigned s2[3], c2[3];
            csa(s2[0], c2[0], s1[0], s1[1], s1[2]);
            csa(s2[1], c2[1], s1[3], s1[4], s1[5]);
            csa(s2[2], c2[2], s1[6], s1[7], xk24);
            unsigned b0v, c3v;
            csa(b0v, c3v, s2[0], s2[1], s2[2]);
            unsigned s4[4], c4a[4];
            csa(s4[0], c4a[0], c1[0], c1[1], c1[2]);
            csa(s4[1], c4a[1], c1[3], c1[4], c1[5]);
            csa(s4[2], c4a[2], c1[6], c1[7], c2[0]);
            csa(s4[3], c4a[3], c2[1], c2[2], c3v);
            unsigned s5, c5;
            csa(s5, c5, s4[0], s4[1], s4[2]);
            unsigned b1v = s5 ^ s4[3];
            unsigned c6 = s5 & s4[3];
            unsigned s7a, c7a, s7b, c7b;
            csa(s7a, c7a, c4a[0], c4a[1], c4a[2]);
            csa(s7b, c7b, c4a[3], c5, c6);
            unsigned b2v = s7a ^ s7b;
            unsigned c8 = s7a & s7b;
            unsigned b3v, b4v;
            csa(b3v, b4v, c7a, c7b, c8);

            // count <= 12  <=>  !(b4 | (b3 & b2 & (b1 | b0)))
            unsigned t1x = b1v | b0v;
            unsigned t2x = b3v & b2v & t1x;
            unsigned m = ~(b4v | t2x);

            m |= __shfl_xor_sync(0xffffffffu, m, 1);     // merge cr=0/1
            if (cr == 0) {
                unsigned v = (m | (m >> 1)) & 0x55555555u;   // horizontal pool
                v = (v | (v >> 1)) & 0x33333333u;            // compact even bits
                v = (v | (v >> 2)) & 0x0F0F0F0Fu;
                v = (v | (v >> 4)) & 0x00FF00FFu;
                v = ((v | (v >> 8)) & 0x0000FFFFu) & 0x3FFFu;
                sc1[img][py][oc] = v;
            }
        }
    }
    __syncthreads();

    // ---- stage 3: conv2 + pool + ternarize (IPB*25 = 200 cells) ----
    if (tid < imax * 25) {
        int img = tid / 25, cell = tid % 25;
        int py = cell / 5, px = cell % 5;
        int ox0 = 2 * px;

        unsigned wpk[4][5];
#pragma unroll
        for (int q = 0; q < 4; q++)
#pragma unroll
            for (int w = 0; w < 5; w++) wpk[q][w] = 0u;

#pragma unroll
        for (int icp = 0; icp < 3; icp++) {
            unsigned ra[6], rb[6];
#pragma unroll
            for (int k = 0; k < 6; k++) {
                uint2 v = *(const uint2*)&sc1[img][2 * py + k][icp * 2];
                ra[k] = v.x; rb[k] = v.y;
            }
#pragma unroll
            for (int h = 0; h < 2; h++) {
                int ox = ox0 + h;
                unsigned va0 = 0, vb0 = 0;
#pragma unroll
                for (int j = 0; j < 5; j++) {
                    va0 |= ((ra[j] >> ox) & 31u) << (5 * j);
                    vb0 |= ((rb[j] >> ox) & 31u) << (5 * j);
                }
                unsigned va1 = (va0 >> 5) | (((ra[5] >> ox) & 31u) << 20);
                unsigned vb1 = (vb0 >> 5) | (((rb[5] >> ox) & 31u) << 20);
                if (icp == 0) {
                    wpk[h][0]     |= va0 | (vb0 << 25);
                    wpk[h][1]     |= vb0 >> 7;
                    wpk[2 + h][0] |= va1 | (vb1 << 25);
                    wpk[2 + h][1] |= vb1 >> 7;
                } else if (icp == 1) {
                    wpk[h][1]     |= va0 << 18;
                    wpk[h][2]     |= (va0 >> 14) | (vb0 << 11);
                    wpk[h][3]     |= vb0 >> 21;
                    wpk[2 + h][1] |= va1 << 18;
                    wpk[2 + h][2] |= (va1 >> 14) | (vb1 << 11);
                    wpk[2 + h][3] |= vb1 >> 21;
                } else {
                    wpk[h][3]     |= (va0 << 4) | (vb0 << 29);
                    wpk[h][4]     |= vb0 >> 3;
                    wpk[2 + h][3] |= (va1 << 4) | (vb1 << 29);
                    wpk[2 + h][4] |= vb1 >> 3;
                }
            }
        }

        unsigned word = 0;
        uint4 wa = sw4[0][0];
        unsigned w4v = sw4[0][1].x;
#pragma unroll
        for (int oc = 0; oc < 16; oc++) {
            uint4 wan;
            unsigned w4n;
            if (oc < 15) { wan = sw4[oc + 1][0]; w4n = sw4[oc + 1][1].x; }
            int d[4];
#pragma unroll
            for (int q = 0; q < 4; q++) {
                unsigned x0 = wpk[q][0] ^ wa.x;
                unsigned x1 = wpk[q][1] ^ wa.y;
                unsigned x2 = wpk[q][2] ^ wa.z;
                unsigned x3 = wpk[q][3] ^ wa.w;
                unsigned x4 = wpk[q][4] ^ w4v;
                unsigned sA, cA, sB, cB;
                csa(sA, cA, x0, x1, x2);
                csa(sB, cB, sA, x3, x4);
                d[q] = __popc(sB) + 2 * (__popc(cA) + __popc(cB));
            }
            int m = min(min(d[0], d[1]), min(d[2], d[3]));
            if (m <= 74) word |= 1u << oc;
            if (m != 75) word |= 1u << (16 + oc);
            if (oc < 15) { wa = wan; w4v = w4n; }
        }
        ss2[img][cell] = word;
    }
    __syncthreads();

    // ---- stage 4: fc1 -> fc2 -> fc3, one warp per image ----
    {
        int img = warp;
        if (img < imax) {
            unsigned W = (lane < 25) ? ss2[img][lane] : 0u;
            unsigned sp[16], sm[16];
#pragma unroll
            for (int oc = 0; oc < 16; oc++) {
                sp[oc] = __ballot_sync(0xffffffffu, (W >> oc) & 1u);
                sm[oc] = __ballot_sync(0xffffffffu, (W >> (16 + oc)) & 1u);
            }
            int M1;
            {
                unsigned sA, cA, sB, cB, sC, cC, sD, cD;
                csa(sA, cA, sm[0], sm[1], sm[2]);
                csa(sB, cB, sm[3], sm[4], sm[5]);
                csa(sC, cC, sA, sB, sm[6]);
                csa(sD, cD, cA, cB, cC);
                M1 = __popc(sC) + __popc(sm[7]) + 2 * __popc(sD) + 4 * __popc(cD);
                csa(sA, cA, sm[8], sm[9], sm[10]);
                csa(sB, cB, sm[11], sm[12], sm[13]);
                csa(sC, cC, sA, sB, sm[14]);
                csa(sD, cD, cA, cB, cC);
                M1 += __popc(sC) + __popc(sm[15]) + 2 * __popc(sD) + 4 * __popc(cD);
            }

            unsigned p2s[4], p2m[4];
#pragma unroll
            for (int k = 0; k < 4; k++) {
                int n = k * 32 + lane;
                int v = 0;
                bool valid = (n < 120);
                if (valid) {
                    unsigned t[16];
#pragma unroll
                    for (int i = 0; i < 16; i++)
                        t[i] = (~(sp[i] ^ s1w[n * 17 + i])) & sm[i];
                    unsigned sA, cA, sB, cB, sC, cC, sD, cD;
                    csa(sA, cA, t[0], t[1], t[2]);
                    csa(sB, cB, t[3], t[4], t[5]);
                    csa(sC, cC, sA, sB, t[6]);
                    csa(sD, cD, cA, cB, cC);
                    int p = __popc(sC) + __popc(t[7]) + 2 * __popc(sD) + 4 * __popc(cD);
                    csa(sA, cA, t[8], t[9], t[10]);
                    csa(sB, cB, t[11], t[12], t[13]);
                    csa(sC, cC, sA, sB, t[14]);
                    csa(sD, cD, cA, cB, cC);
                    p += __popc(sC) + __popc(t[15]) + 2 * __popc(sD) + 4 * __popc(cD);
                    v = 2 * p - M1;
                }
                p2s[k] = __ballot_sync(0xffffffffu, valid && (v > 0));
                p2m[k] = __ballot_sync(0xffffffffu, valid && (v != 0));
            }
            int M2;
            {
                unsigned s, c;
                csa(s, c, p2m[0], p2m[1], p2m[2]);
                M2 = __popc(s) + __popc(p2m[3]) + 2 * __popc(c);
            }

            unsigned p3s[3], p3m[3];
#pragma unroll
            for (int k = 0; k < 3; k++) {
                int n = k * 32 + lane;
                int v = 0;
                bool valid = (n < 84);
                if (valid) {
                    unsigned t0 = (~(p2s[0] ^ s2w[n * 5 + 0])) & p2m[0];
                    unsigned t1 = (~(p2s[1] ^ s2w[n * 5 + 1])) & p2m[1];
                    unsigned t2 = (~(p2s[2] ^ s2w[n * 5 + 2])) & p2m[2];
                    unsigned t3 = (~(p2s[3] ^ s2w[n * 5 + 3])) & p2m[3];
                    unsigned s, c;
                    csa(s, c, t0, t1, t2);
                    int p = __popc(s) + __popc(t3) + 2 * __popc(c);
                    v = 2 * p - M2;
                }
                p3s[k] = __ballot_sync(0xffffffffu, valid && (v > 0));
                p3m[k] = __ballot_sync(0xffffffffu, valid && (v != 0));
            }
            int M3;
            {
                unsigned s, c;
                csa(s, c, p3m[0], p3m[1], p3m[2]);
                M3 = __popc(s) + 2 * __popc(c);
            }

            if (lane < 10) {
                unsigned t0 = (~(p3s[0] ^ s3w[lane * 3 + 0])) & p3m[0];
                unsigned t1 = (~(p3s[1] ^ s3w[lane * 3 + 1])) & p3m[1];
                unsigned t2 = (~(p3s[2] ^ s3w[lane * 3 + 2])) & p3m[2];
                unsigned s, c;
                csa(s, c, t0, t1, t2);
                int p = __popc(s) + 2 * __popc(c);
                out[(size_t)(b0 + img) * 10 + lane] = (float)(2 * p - M3);
            }
        }
    }
}

// ---------------- launch ----------------
extern "C" void kernel_launch(void* const* d_in, const int* in_sizes, int n_in,
                              void* d_out, int out_size) {
    const float* x  = (const float*)d_in[0];
    const float* w1 = (const float*)d_in[1];
    const float* w2 = (const float*)d_in[2];
    const float* f1 = (const float*)d_in[3];
    const float* f2 = (const float*)d_in[4];
    const float* f3 = (const float*)d_in[5];
    float* out = (float*)d_out;

    int B = in_sizes[0] / 1024;
    if (B > B_MAX) B = B_MAX;

    pack_weights<<<289, 256>>>(w1, w2, f1, f2, f3);

    int blocks = (B + IPB - 1) / IPB;
    mega_k<<<blocks, 256>>>(x, out, B);
}